// round 2
// baseline (speedup 1.0000x reference)
#include <cuda_runtime.h>
#include <math.h>

// ---------------------------------------------------------------------------
// Problem constants (batch already halved: cat(x,x) duplicates, out[:b] keeps half)
//   B=32, C=512, N=256 (seq), H=8, P=256 (patch flat), HC=4096
// ---------------------------------------------------------------------------

// Scratch (device globals; no cudaMalloc allowed)
__device__ float g_emb[32 * 256 * 512];      //  (b, n, c)
__device__ float g_xn [32 * 256 * 512];      //  LN outputs (reused for LN2 output)
__device__ float g_q  [32 * 256 * 4096];     //  (b, n, h*512+i); reused for ctx2
__device__ float g_k  [32 * 256 * 4096];
__device__ float g_v  [32 * 256 * 4096];
__device__ float g_sc [32 * 8 * 512 * 512];  //  scores -> attn in place
__device__ float g_ob [32 * 256 * 512];      //  out-proj + residual
__device__ float g_st [32 * 8 * 2];          //  instance-norm mean/rstd
__device__ float g_wqT[4096 * 512];
__device__ float g_wkT[4096 * 512];
__device__ float g_wvT[4096 * 512];
__device__ float g_woT[512 * 4096];          //  woT[o,h*512+c] = wo[c*8+h, o]

__device__ __forceinline__ float gelu_f(float x) {
    return 0.5f * x * (1.0f + erff(x * 0.70710678118654752f));
}

// Packed fp32x2 FMA (sm_100+): d = a * b + d elementwise on 2-float packs.
#define FFMA2(d, a, b) asm("fma.rn.f32x2 %0, %1, %2, %0;" : "+l"(d) : "l"(a), "l"(b))

__device__ __forceinline__ float2 unpack2(unsigned long long v) {
    float2 r;
    asm("mov.b64 {%0, %1}, %2;" : "=f"(r.x), "=f"(r.y) : "l"(v));
    return r;
}

// ---------------------------------------------------------------------------
// Epilogue: acc[4][4] packed pairs -> 4 rows x 8 cols.
// EPI: 0 none | 1 +bias[m] | 2 +res[m*ldc+n] | 3 +bias[m] then exact GELU
// ---------------------------------------------------------------------------
template <int EPI>
__device__ __forceinline__ void epi_store2(unsigned long long acc[4][4], float* Cb,
                                           int ldc, int m0, int n0, int tx, int ty,
                                           const float* __restrict__ epp) {
#pragma unroll
    for (int i = 0; i < 4; ++i) {
        const int m = m0 + (ty << 2) + i;
        float f[8];
#pragma unroll
        for (int j = 0; j < 4; ++j) {
            const float2 p = unpack2(acc[i][j]);
            f[2 * j] = p.x; f[2 * j + 1] = p.y;
        }
        if (EPI == 1 || EPI == 3) {
            const float bi = epp[m];
#pragma unroll
            for (int j = 0; j < 8; ++j) f[j] += bi;
        }
        if (EPI == 2) {
            const float4 r0 = *reinterpret_cast<const float4*>(epp + (long)m * ldc + n0 + (tx << 3));
            const float4 r1 = *reinterpret_cast<const float4*>(epp + (long)m * ldc + n0 + (tx << 3) + 4);
            f[0] += r0.x; f[1] += r0.y; f[2] += r0.z; f[3] += r0.w;
            f[4] += r1.x; f[5] += r1.y; f[6] += r1.z; f[7] += r1.w;
        }
        if (EPI == 3) {
#pragma unroll
            for (int j = 0; j < 8; ++j) f[j] = gelu_f(f[j]);
        }
        *reinterpret_cast<float4*>(Cb + (long)m * ldc + n0 + (tx << 3)) =
            make_float4(f[0], f[1], f[2], f[3]);
        *reinterpret_cast<float4*>(Cb + (long)m * ldc + n0 + (tx << 3) + 4) =
            make_float4(f[4], f[5], f[6], f[7]);
    }
}

// ---------------------------------------------------------------------------
// NT GEMM (f32x2): C[m,n] = sum_k A[m,k]*B[n,k], K-contiguous operands.
// Tile 64(M) x 128(N), BK=16, 256 threads, 4m x 8n per thread.
// A stored DUPLICATED in smem ({a,a}) so FFMA2 broadcast operand is a plain LDS.
// Double-buffered with register prefetch. M%64==0, N%128==0, K%16==0.
// ---------------------------------------------------------------------------
template <int EPI>
__global__ void __launch_bounds__(256) gemm_nt2(
    const float* __restrict__ A, int lda, long sAb, long sAh,
    const float* __restrict__ B, int ldb, long sBb, long sBh,
    float* __restrict__ C, int ldc, long sCb, long sCh,
    int K, int Hdiv, const float* __restrict__ ep, long sEpb) {
    __shared__ float As2[2][16][132];   // [buf][k][2*m + {0,1}] duplicated
    __shared__ float Bs [2][16][132];   // [buf][k][n]
    const int z = blockIdx.z;
    const int b = z / Hdiv, h = z - b * Hdiv;
    const float* Ab = A + (long)b * sAb + (long)h * sAh;
    const float* Bb = B + (long)b * sBb + (long)h * sBh;
    float* Cb = C + (long)b * sCb + (long)h * sCh;
    const float* epp = ep ? (ep + (long)b * sEpb) : ep;

    const int m0 = blockIdx.y << 6;
    const int n0 = blockIdx.x << 7;
    const int tid = threadIdx.x;
    const int tx = tid & 15, ty = tid >> 4;
    const int ar = tid >> 2;            // 0..63 (A row within tile)
    const int ak = (tid & 3) << 2;      // k offset (float4)

    const int nCh = K >> 4;
    const float* Arow = Ab + (long)(m0 + ar) * lda + ak;
    const float* Brow0 = Bb + (long)(n0 + ar) * ldb + ak;
    const float* Brow1 = Bb + (long)(n0 + ar + 64) * ldb + ak;

    float4 pa = *reinterpret_cast<const float4*>(Arow);
    float4 pb0 = *reinterpret_cast<const float4*>(Brow0);
    float4 pb1 = *reinterpret_cast<const float4*>(Brow1);
    {
        const float va[4] = {pa.x, pa.y, pa.z, pa.w};
        const float v0[4] = {pb0.x, pb0.y, pb0.z, pb0.w};
        const float v1[4] = {pb1.x, pb1.y, pb1.z, pb1.w};
#pragma unroll
        for (int j = 0; j < 4; ++j) {
            *reinterpret_cast<float2*>(&As2[0][ak + j][2 * ar]) = make_float2(va[j], va[j]);
            Bs[0][ak + j][ar] = v0[j];
            Bs[0][ak + j][ar + 64] = v1[j];
        }
    }
    __syncthreads();

    unsigned long long acc[4][4] = {};
    for (int c = 0; c < nCh; ++c) {
        const int buf = c & 1;
        if (c + 1 < nCh) {
            const int k0 = (c + 1) << 4;
            pa  = *reinterpret_cast<const float4*>(Arow + k0);
            pb0 = *reinterpret_cast<const float4*>(Brow0 + k0);
            pb1 = *reinterpret_cast<const float4*>(Brow1 + k0);
        }
#pragma unroll
        for (int kk = 0; kk < 16; ++kk) {
            const ulonglong2 a01 = *reinterpret_cast<const ulonglong2*>(&As2[buf][kk][ty << 3]);
            const ulonglong2 a23 = *reinterpret_cast<const ulonglong2*>(&As2[buf][kk][(ty << 3) + 4]);
            const ulonglong2 b01 = *reinterpret_cast<const ulonglong2*>(&Bs[buf][kk][tx << 3]);
            const ulonglong2 b23 = *reinterpret_cast<const ulonglong2*>(&Bs[buf][kk][(tx << 3) + 4]);
            FFMA2(acc[0][0], a01.x, b01.x); FFMA2(acc[0][1], a01.x, b01.y);
            FFMA2(acc[0][2], a01.x, b23.x); FFMA2(acc[0][3], a01.x, b23.y);
            FFMA2(acc[1][0], a01.y, b01.x); FFMA2(acc[1][1], a01.y, b01.y);
            FFMA2(acc[1][2], a01.y, b23.x); FFMA2(acc[1][3], a01.y, b23.y);
            FFMA2(acc[2][0], a23.x, b01.x); FFMA2(acc[2][1], a23.x, b01.y);
            FFMA2(acc[2][2], a23.x, b23.x); FFMA2(acc[2][3], a23.x, b23.y);
            FFMA2(acc[3][0], a23.y, b01.x); FFMA2(acc[3][1], a23.y, b01.y);
            FFMA2(acc[3][2], a23.y, b23.x); FFMA2(acc[3][3], a23.y, b23.y);
        }
        __syncthreads();
        if (c + 1 < nCh) {
            const int nb = buf ^ 1;
            const float va[4] = {pa.x, pa.y, pa.z, pa.w};
            const float v0[4] = {pb0.x, pb0.y, pb0.z, pb0.w};
            const float v1[4] = {pb1.x, pb1.y, pb1.z, pb1.w};
#pragma unroll
            for (int j = 0; j < 4; ++j) {
                *reinterpret_cast<float2*>(&As2[nb][ak + j][2 * ar]) = make_float2(va[j], va[j]);
                Bs[nb][ak + j][ar] = v0[j];
                Bs[nb][ak + j][ar + 64] = v1[j];
            }
            __syncthreads();
        }
    }
    epi_store2<EPI>(acc, Cb, ldc, m0, n0, tx, ty, epp);
}

// ---------------------------------------------------------------------------
// TN GEMM (f32x2): C[m,n] = sum_k A[k*lda+m]*B[k*ldb+n] (M/N-contiguous).
// Same tile/threading as gemm_nt2.
// ---------------------------------------------------------------------------
template <int EPI>
__global__ void __launch_bounds__(256) gemm_tn2(
    const float* __restrict__ A, int lda, long sAb, long sAh,
    const float* __restrict__ B, int ldb, long sBb, long sBh,
    float* __restrict__ C, int ldc, long sCb, long sCh,
    int K, int Hdiv, const float* __restrict__ ep, long sEpb) {
    __shared__ float As2[2][16][132];
    __shared__ float Bs [2][16][132];
    const int z = blockIdx.z;
    const int b = z / Hdiv, h = z - b * Hdiv;
    const float* Ab = A + (long)b * sAb + (long)h * sAh;
    const float* Bb = B + (long)b * sBb + (long)h * sBh;
    float* Cb = C + (long)b * sCb + (long)h * sCh;
    const float* epp = ep ? (ep + (long)b * sEpb) : ep;

    const int m0 = blockIdx.y << 6;
    const int n0 = blockIdx.x << 7;
    const int tid = threadIdx.x;
    const int tx = tid & 15, ty = tid >> 4;
    const int kr = tid >> 4;            // 0..15 (k row)
    const int mc = (tid & 15) << 2;     // 0..60 (A m offset, float4)
    const int nc = (tid & 15) << 3;     // 0..120 (B n offset, 2x float4)

    const int nCh = K >> 4;
    const float* Arow = Ab + (long)kr * lda + m0 + mc;
    const float* Brow = Bb + (long)kr * ldb + n0 + nc;

    float4 pa = *reinterpret_cast<const float4*>(Arow);
    float4 pb0 = *reinterpret_cast<const float4*>(Brow);
    float4 pb1 = *reinterpret_cast<const float4*>(Brow + 4);
    {
        const float va[4] = {pa.x, pa.y, pa.z, pa.w};
#pragma unroll
        for (int j = 0; j < 4; ++j)
            *reinterpret_cast<float2*>(&As2[0][kr][2 * (mc + j)]) = make_float2(va[j], va[j]);
        *reinterpret_cast<float4*>(&Bs[0][kr][nc]) = pb0;
        *reinterpret_cast<float4*>(&Bs[0][kr][nc + 4]) = pb1;
    }
    __syncthreads();

    unsigned long long acc[4][4] = {};
    for (int c = 0; c < nCh; ++c) {
        const int buf = c & 1;
        if (c + 1 < nCh) {
            const long k0 = (long)((c + 1) << 4);
            pa  = *reinterpret_cast<const float4*>(Arow + k0 * lda);
            pb0 = *reinterpret_cast<const float4*>(Brow + k0 * ldb);
            pb1 = *reinterpret_cast<const float4*>(Brow + k0 * ldb + 4);
        }
#pragma unroll
        for (int kk = 0; kk < 16; ++kk) {
            const ulonglong2 a01 = *reinterpret_cast<const ulonglong2*>(&As2[buf][kk][ty << 3]);
            const ulonglong2 a23 = *reinterpret_cast<const ulonglong2*>(&As2[buf][kk][(ty << 3) + 4]);
            const ulonglong2 b01 = *reinterpret_cast<const ulonglong2*>(&Bs[buf][kk][tx << 3]);
            const ulonglong2 b23 = *reinterpret_cast<const ulonglong2*>(&Bs[buf][kk][(tx << 3) + 4]);
            FFMA2(acc[0][0], a01.x, b01.x); FFMA2(acc[0][1], a01.x, b01.y);
            FFMA2(acc[0][2], a01.x, b23.x); FFMA2(acc[0][3], a01.x, b23.y);
            FFMA2(acc[1][0], a01.y, b01.x); FFMA2(acc[1][1], a01.y, b01.y);
            FFMA2(acc[1][2], a01.y, b23.x); FFMA2(acc[1][3], a01.y, b23.y);
            FFMA2(acc[2][0], a23.x, b01.x); FFMA2(acc[2][1], a23.x, b01.y);
            FFMA2(acc[2][2], a23.x, b23.x); FFMA2(acc[2][3], a23.x, b23.y);
            FFMA2(acc[3][0], a23.y, b01.x); FFMA2(acc[3][1], a23.y, b01.y);
            FFMA2(acc[3][2], a23.y, b23.x); FFMA2(acc[3][3], a23.y, b23.y);
        }
        __syncthreads();
        if (c + 1 < nCh) {
            const int nb = buf ^ 1;
            const float va[4] = {pa.x, pa.y, pa.z, pa.w};
#pragma unroll
            for (int j = 0; j < 4; ++j)
                *reinterpret_cast<float2*>(&As2[nb][kr][2 * (mc + j)]) = make_float2(va[j], va[j]);
            *reinterpret_cast<float4*>(&Bs[nb][kr][nc]) = pb0;
            *reinterpret_cast<float4*>(&Bs[nb][kr][nc + 4]) = pb1;
            __syncthreads();
        }
    }
    epi_store2<EPI>(acc, Cb, ldc, m0, n0, tx, ty, epp);
}

// ---------------------------------------------------------------------------
// LayerNorm over last dim (512). One warp per row, float4 vectorized.
// ---------------------------------------------------------------------------
__global__ void __launch_bounds__(256) ln_kernel(
    const float* __restrict__ in, float* __restrict__ out,
    const float* __restrict__ gamma, const float* __restrict__ beta, float eps) {
    const int warp = blockIdx.x * (blockDim.x >> 5) + (threadIdx.x >> 5);
    const int lane = threadIdx.x & 31;
    const float4* r = reinterpret_cast<const float4*>(in + (long)warp * 512);
    float4 v[4];
    float s = 0.f, s2 = 0.f;
#pragma unroll
    for (int i = 0; i < 4; ++i) {
        v[i] = r[lane + (i << 5)];
        s  += v[i].x + v[i].y + v[i].z + v[i].w;
        s2 += v[i].x * v[i].x + v[i].y * v[i].y + v[i].z * v[i].z + v[i].w * v[i].w;
    }
#pragma unroll
    for (int o = 16; o > 0; o >>= 1) {
        s  += __shfl_xor_sync(0xffffffffu, s, o);
        s2 += __shfl_xor_sync(0xffffffffu, s2, o);
    }
    const float mu = s * (1.f / 512.f);
    const float rstd = rsqrtf(s2 * (1.f / 512.f) - mu * mu + eps);
    float4* w = reinterpret_cast<float4*>(out + (long)warp * 512);
#pragma unroll
    for (int i = 0; i < 4; ++i) {
        const float4 g4 = reinterpret_cast<const float4*>(gamma)[lane + (i << 5)];
        const float4 b4 = reinterpret_cast<const float4*>(beta)[lane + (i << 5)];
        float4 o4;
        o4.x = (v[i].x - mu) * rstd * g4.x + b4.x;
        o4.y = (v[i].y - mu) * rstd * g4.y + b4.y;
        o4.z = (v[i].z - mu) * rstd * g4.z + b4.z;
        o4.w = (v[i].w - mu) * rstd * g4.w + b4.w;
        w[lane + (i << 5)] = o4;
    }
}

// ---------------------------------------------------------------------------
// InstanceNorm stats: per (b,h), mean/rstd over 512x512.
// ---------------------------------------------------------------------------
__global__ void __launch_bounds__(256) inorm_stats(const float* __restrict__ sc,
                                                   float* __restrict__ stats) {
    __shared__ float sh[256], sh2[256];
    const int z = blockIdx.x;
    const float4* p = reinterpret_cast<const float4*>(sc + (long)z * 262144);
    float s = 0.f, s2 = 0.f;
    for (int i = threadIdx.x; i < 65536; i += 256) {
        const float4 v = p[i];
        s  += v.x + v.y + v.z + v.w;
        s2 += v.x * v.x + v.y * v.y + v.z * v.z + v.w * v.w;
    }
    sh[threadIdx.x] = s; sh2[threadIdx.x] = s2;
    __syncthreads();
    for (int o = 128; o > 0; o >>= 1) {
        if (threadIdx.x < o) { sh[threadIdx.x] += sh[threadIdx.x + o]; sh2[threadIdx.x] += sh2[threadIdx.x + o]; }
        __syncthreads();
    }
    if (threadIdx.x == 0) {
        const float mu = sh[0] * (1.f / 262144.f);
        const float var = sh2[0] * (1.f / 262144.f) - mu * mu;
        stats[z * 2 + 0] = mu;
        stats[z * 2 + 1] = rsqrtf(var + 1e-5f);
    }
}

// ---------------------------------------------------------------------------
// Fused instance-norm-apply + softmax over rows of 512, in place. One warp/row.
// ---------------------------------------------------------------------------
__global__ void __launch_bounds__(256) softmax_rows(float* __restrict__ sc,
                                                    const float* __restrict__ stats) {
    const int warp = blockIdx.x * (blockDim.x >> 5) + (threadIdx.x >> 5);
    const int lane = threadIdx.x & 31;
    const int z = warp >> 9;
    const float mu = stats[z * 2 + 0];
    const float rstd = stats[z * 2 + 1];
    float4* row = reinterpret_cast<float4*>(sc + (long)warp * 512);
    float4 v[4];
    float mx = -1e30f;
#pragma unroll
    for (int i = 0; i < 4; ++i) {
        v[i] = row[lane + (i << 5)];
        v[i].x = (v[i].x - mu) * rstd; v[i].y = (v[i].y - mu) * rstd;
        v[i].z = (v[i].z - mu) * rstd; v[i].w = (v[i].w - mu) * rstd;
        mx = fmaxf(mx, fmaxf(fmaxf(v[i].x, v[i].y), fmaxf(v[i].z, v[i].w)));
    }
#pragma unroll
    for (int o = 16; o > 0; o >>= 1) mx = fmaxf(mx, __shfl_xor_sync(0xffffffffu, mx, o));
    float s = 0.f;
#pragma unroll
    for (int i = 0; i < 4; ++i) {
        v[i].x = __expf(v[i].x - mx); v[i].y = __expf(v[i].y - mx);
        v[i].z = __expf(v[i].z - mx); v[i].w = __expf(v[i].w - mx);
        s += v[i].x + v[i].y + v[i].z + v[i].w;
    }
#pragma unroll
    for (int o = 16; o > 0; o >>= 1) s += __shfl_xor_sync(0xffffffffu, s, o);
    const float inv = 1.f / s;
#pragma unroll
    for (int i = 0; i < 4; ++i) {
        v[i].x *= inv; v[i].y *= inv; v[i].z *= inv; v[i].w *= inv;
        row[lane + (i << 5)] = v[i];
    }
}

// ---------------------------------------------------------------------------
// Weight pre-processing
// ---------------------------------------------------------------------------
__global__ void __launch_bounds__(256) transpose_rc(const float* __restrict__ in,
                                                    float* __restrict__ out,
                                                    int rows, int cols) {
    // out[c*rows + r] = in[r*cols + c]
    __shared__ float t[32][33];
    const int c0 = blockIdx.x << 5, r0 = blockIdx.y << 5;
    const int tx = threadIdx.x, ty = threadIdx.y;  // 32 x 8
#pragma unroll
    for (int j = 0; j < 32; j += 8) t[ty + j][tx] = in[(long)(r0 + ty + j) * cols + c0 + tx];
    __syncthreads();
#pragma unroll
    for (int j = 0; j < 32; j += 8) out[(long)(c0 + ty + j) * rows + r0 + tx] = t[tx][ty + j];
}

__global__ void __launch_bounds__(256) permute_wo(const float* __restrict__ wo,
                                                  float* __restrict__ woT) {
    // woT[o*4096 + h*512 + c] = wo[(c*8+h)*512 + o]
    const long idx = (long)blockIdx.x * 256 + threadIdx.x;  // over 512*4096
    const int o = (int)(idx & 511);
    const int ch = (int)(idx >> 9);
    const int h = ch & 7;
    const int c = ch >> 3;
    woT[(long)o * 4096 + h * 512 + c] = wo[idx];
}

// ---------------------------------------------------------------------------
// Host launcher
// ---------------------------------------------------------------------------
extern "C" void kernel_launch(void* const* d_in, const int* in_sizes, int n_in,
                              void* d_out, int out_size) {
    const float* x      = (const float*)d_in[0];
    const float* proj_w = (const float*)d_in[1];
    const float* proj_b = (const float*)d_in[2];
    const float* ln1_g  = (const float*)d_in[3];
    const float* ln1_b  = (const float*)d_in[4];
    const float* wq     = (const float*)d_in[5];
    const float* wk     = (const float*)d_in[6];
    const float* wv     = (const float*)d_in[7];
    const float* wo     = (const float*)d_in[8];
    const float* ln2_g  = (const float*)d_in[9];
    const float* ln2_b  = (const float*)d_in[10];
    const float* mo_w   = (const float*)d_in[11];
    const float* mo_b   = (const float*)d_in[12];
    float* out = (float*)d_out;

    float *emb, *xn, *q, *k, *v, *sc, *ob, *st, *wqT, *wkT, *wvT, *woT;
    cudaGetSymbolAddress((void**)&emb, g_emb);
    cudaGetSymbolAddress((void**)&xn,  g_xn);
    cudaGetSymbolAddress((void**)&q,   g_q);
    cudaGetSymbolAddress((void**)&k,   g_k);
    cudaGetSymbolAddress((void**)&v,   g_v);
    cudaGetSymbolAddress((void**)&sc,  g_sc);
    cudaGetSymbolAddress((void**)&ob,  g_ob);
    cudaGetSymbolAddress((void**)&st,  g_st);
    cudaGetSymbolAddress((void**)&wqT, g_wqT);
    cudaGetSymbolAddress((void**)&wkT, g_wkT);
    cudaGetSymbolAddress((void**)&wvT, g_wvT);
    cudaGetSymbolAddress((void**)&woT, g_woT);

    // Weight prep
    transpose_rc<<<dim3(128, 16), dim3(32, 8)>>>(wq, wqT, 512, 4096);
    transpose_rc<<<dim3(128, 16), dim3(32, 8)>>>(wk, wkT, 512, 4096);
    transpose_rc<<<dim3(128, 16), dim3(32, 8)>>>(wv, wvT, 512, 4096);
    permute_wo<<<8192, 256>>>(wo, woT);

    // 1) Patch embed: emb[b,n,c] = sum_p proj_w[n,p]*x[b,c,p] + proj_b[n]
    //    M=256, N=512, K=256
    gemm_nt2<1><<<dim3(4, 4, 32), 256>>>(proj_w, 256, 0, 0,
                                         x, 256, 131072L, 0,
                                         emb, 512, 131072L, 0,
                                         256, 1, proj_b, 0);
    // 2) LN1
    ln_kernel<<<1024, 256>>>(emb, xn, ln1_g, ln1_b, 1e-6f);
    // 3) Q,K,V: M=256, N=4096, K=512 per batch (NT vs pre-transposed weights)
    gemm_nt2<0><<<dim3(32, 4, 32), 256>>>(xn, 512, 131072L, 0, wqT, 512, 0, 0,
                                          q, 4096, 1048576L, 0, 512, 1, nullptr, 0);
    gemm_nt2<0><<<dim3(32, 4, 32), 256>>>(xn, 512, 131072L, 0, wkT, 512, 0, 0,
                                          k, 4096, 1048576L, 0, 512, 1, nullptr, 0);
    gemm_nt2<0><<<dim3(32, 4, 32), 256>>>(xn, 512, 131072L, 0, wvT, 512, 0, 0,
                                          v, 4096, 1048576L, 0, 512, 1, nullptr, 0);
    // 4) Scores: per (b,h) M=512, N=512, K=256 (TN)
    gemm_tn2<0><<<dim3(4, 8, 256), 256>>>(q, 4096, 1048576L, 512, k, 4096, 1048576L, 512,
                                          sc, 512, 2097152L, 262144L, 256, 8, nullptr, 0);
    // 5) InstanceNorm stats + fused normalize+softmax (in place)
    inorm_stats<<<256, 256>>>(sc, st);
    softmax_rows<<<16384, 256>>>(sc, st);
    // 6) ctx2[b,n,h,i] = sum_j v[b,n,h,j]*attn[b,h,i,j]: M=256, N=512, K=512 per (b,h)
    gemm_nt2<0><<<dim3(4, 4, 256), 256>>>(v, 4096, 1048576L, 512, sc, 512, 2097152L, 262144L,
                                          q, 4096, 1048576L, 512, 512, 8, nullptr, 0);
    // 7) Out-proj + residual: M=256, N=512, K=4096
    gemm_nt2<2><<<dim3(4, 4, 32), 256>>>(q, 4096, 1048576L, 0, woT, 4096, 0, 0,
                                         ob, 512, 131072L, 0, 4096, 1, emb, 131072L);
    // 8) LN2 (reuse g_xn)
    ln_kernel<<<1024, 256>>>(ob, xn, ln2_g, ln2_b, 1e-6f);
    // 9) 1x1 conv + bias + exact GELU, direct to d_out: M=512, N=256, K=512
    gemm_nt2<3><<<dim3(2, 8, 32), 256>>>(mo_w, 512, 0, 0, xn, 512, 131072L, 0,
                                         out, 256, 131072L, 0, 512, 1, mo_b, 0);
}

// round 4
// speedup vs baseline: 3.2646x; 3.2646x over previous
#include <cuda_runtime.h>
#include <math.h>

// ---------------------------------------------------------------------------
// Problem constants (batch already halved: cat(x,x) duplicates, out[:b] keeps half)
//   B=32, C=512, N=256 (seq), H=8, P=256 (patch flat), HC=4096
// ---------------------------------------------------------------------------

__device__ float g_emb[32 * 256 * 512];      //  (b, n, c)
__device__ float g_xn [32 * 256 * 512];      //  LN outputs (reused for LN2 output)
__device__ float g_q  [32 * 256 * 4096];     //  (b, n, h*512+i); reused for ctx2
__device__ float g_k  [32 * 256 * 4096];
__device__ float g_v  [32 * 256 * 4096];
__device__ float g_sc [32 * 8 * 512 * 512];  //  scores -> attn in place
__device__ float g_ob [32 * 256 * 512];      //  out-proj + residual
__device__ float g_st [32 * 8 * 2];          //  instance-norm mean/rstd
__device__ float g_wqT[4096 * 512];
__device__ float g_wkT[4096 * 512];
__device__ float g_wvT[4096 * 512];
__device__ float g_woT[512 * 4096];          //  woT[o,h*512+c] = wo[c*8+h, o]

__device__ __forceinline__ float gelu_f(float x) {
    return 0.5f * x * (1.0f + erff(x * 0.70710678118654752f));
}

__device__ __forceinline__ float tf32f(float f) {
    unsigned u;
    asm("cvt.rna.tf32.f32 %0, %1;" : "=r"(u) : "f"(f));
    return __uint_as_float(u);
}

#define MMA_TF32(c, a, b)                                                     \
    asm volatile(                                                             \
        "mma.sync.aligned.m16n8k8.row.col.f32.tf32.tf32.f32 "                 \
        "{%0,%1,%2,%3},{%4,%5,%6,%7},{%8,%9},{%0,%1,%2,%3};"                  \
        : "+f"(c[0]), "+f"(c[1]), "+f"(c[2]), "+f"(c[3])                      \
        : "r"(a[0]), "r"(a[1]), "r"(a[2]), "r"(a[3]), "r"(b[0]), "r"(b[1]))

// ---------------------------------------------------------------------------
// Epilogue (scalar stores). Thread owns acc[4][4][4] of warp tile 64x32.
// EPI: 0 none | 1 +bias[m] | 2 +res[m*ldc+n] | 3 +bias[m] then exact GELU
// ---------------------------------------------------------------------------
template <int EPI>
__device__ __forceinline__ void epi_tc(float acc[4][4][4], float* Cb, int ldc,
                                       int m0, int n0, int wm, int wn, int g, int tq,
                                       const float* __restrict__ epp) {
#pragma unroll
    for (int mt = 0; mt < 4; ++mt) {
        const int r1 = m0 + wm * 64 + mt * 16 + g;
        const int r2 = r1 + 8;
        float b1 = 0.f, b2 = 0.f;
        if (EPI == 1 || EPI == 3) { b1 = epp[r1]; b2 = epp[r2]; }
#pragma unroll
        for (int nt = 0; nt < 4; ++nt) {
            const int col = n0 + wn * 32 + nt * 8 + 2 * tq;
            float c0 = acc[mt][nt][0], c1 = acc[mt][nt][1];
            float c2 = acc[mt][nt][2], c3 = acc[mt][nt][3];
            if (EPI == 1 || EPI == 3) { c0 += b1; c1 += b1; c2 += b2; c3 += b2; }
            if (EPI == 2) {
                c0 += epp[(long)r1 * ldc + col];
                c1 += epp[(long)r1 * ldc + col + 1];
                c2 += epp[(long)r2 * ldc + col];
                c3 += epp[(long)r2 * ldc + col + 1];
            }
            if (EPI == 3) {
                c0 = gelu_f(c0); c1 = gelu_f(c1); c2 = gelu_f(c2); c3 = gelu_f(c3);
            }
            Cb[(long)r1 * ldc + col] = c0;
            Cb[(long)r1 * ldc + col + 1] = c1;
            Cb[(long)r2 * ldc + col] = c2;
            Cb[(long)r2 * ldc + col + 1] = c3;
        }
    }
}

// ---------------------------------------------------------------------------
// NT GEMM (tf32 mma): C[m,n] = sum_k A[m,k]*B[n,k], K-contiguous operands.
// Tile 128x128, BK=16, 256 threads (8 warps as 2m x 4n, warp tile 64x32).
// Smem: plain k-major float [16][132]. M,N % 128 == 0, K % 16 == 0.
// ---------------------------------------------------------------------------
template <int EPI>
__global__ void __launch_bounds__(256) gemm_tc_nt(
    const float* __restrict__ A, int lda, long sAb, long sAh,
    const float* __restrict__ B, int ldb, long sBb, long sBh,
    float* __restrict__ C, int ldc, long sCb, long sCh,
    int K, int Hdiv, const float* __restrict__ ep, long sEpb) {
    __shared__ __align__(16) float As[2][16][132];
    __shared__ __align__(16) float Bs[2][16][132];
    const int z = blockIdx.z;
    const int b = z / Hdiv, h = z - b * Hdiv;
    const float* Ab = A + (long)b * sAb + (long)h * sAh;
    const float* Bb = B + (long)b * sBb + (long)h * sBh;
    float* Cb = C + (long)b * sCb + (long)h * sCh;
    const float* epp = ep ? (ep + (long)b * sEpb) : ep;

    const int m0 = blockIdx.y << 7;
    const int n0 = blockIdx.x << 7;
    const int tid = threadIdx.x;
    const int warp = tid >> 5, lane = tid & 31;
    const int wm = warp & 1, wn = warp >> 1;
    const int g = lane >> 2, tq = lane & 3;

    // Loader: lr = row-in-tile (0..63, +64 for second half), lc = k offset.
    const int lr = tid >> 2;
    const int lc = (tid & 3) << 2;
    const float* Ap0 = Ab + (long)(m0 + lr) * lda + lc;
    const float* Ap1 = Ap0 + 64L * lda;
    const float* Bp0 = Bb + (long)(n0 + lr) * ldb + lc;
    const float* Bp1 = Bp0 + 64L * ldb;

    float4 pa0 = *reinterpret_cast<const float4*>(Ap0);
    float4 pa1 = *reinterpret_cast<const float4*>(Ap1);
    float4 pb0 = *reinterpret_cast<const float4*>(Bp0);
    float4 pb1 = *reinterpret_cast<const float4*>(Bp1);

    {
        As[0][lc + 0][lr] = tf32f(pa0.x); As[0][lc + 1][lr] = tf32f(pa0.y);
        As[0][lc + 2][lr] = tf32f(pa0.z); As[0][lc + 3][lr] = tf32f(pa0.w);
        As[0][lc + 0][lr + 64] = tf32f(pa1.x); As[0][lc + 1][lr + 64] = tf32f(pa1.y);
        As[0][lc + 2][lr + 64] = tf32f(pa1.z); As[0][lc + 3][lr + 64] = tf32f(pa1.w);
        Bs[0][lc + 0][lr] = tf32f(pb0.x); Bs[0][lc + 1][lr] = tf32f(pb0.y);
        Bs[0][lc + 2][lr] = tf32f(pb0.z); Bs[0][lc + 3][lr] = tf32f(pb0.w);
        Bs[0][lc + 0][lr + 64] = tf32f(pb1.x); Bs[0][lc + 1][lr + 64] = tf32f(pb1.y);
        Bs[0][lc + 2][lr + 64] = tf32f(pb1.z); Bs[0][lc + 3][lr + 64] = tf32f(pb1.w);
    }
    __syncthreads();

    float acc[4][4][4] = {};
    const int nSt = K >> 4;
    for (int s = 0; s < nSt; ++s) {
        const int buf = s & 1;
        if (s + 1 < nSt) {
            const int k0 = (s + 1) << 4;
            pa0 = *reinterpret_cast<const float4*>(Ap0 + k0);
            pa1 = *reinterpret_cast<const float4*>(Ap1 + k0);
            pb0 = *reinterpret_cast<const float4*>(Bp0 + k0);
            pb1 = *reinterpret_cast<const float4*>(Bp1 + k0);
        }
#pragma unroll
        for (int kb = 0; kb < 2; ++kb) {
            const int k1 = kb * 8 + tq, k2 = k1 + 4;
            unsigned af[4][4];
#pragma unroll
            for (int mt = 0; mt < 4; ++mt) {
                const int row = wm * 64 + mt * 16 + g;
                af[mt][0] = __float_as_uint(As[buf][k1][row]);
                af[mt][1] = __float_as_uint(As[buf][k1][row + 8]);
                af[mt][2] = __float_as_uint(As[buf][k2][row]);
                af[mt][3] = __float_as_uint(As[buf][k2][row + 8]);
            }
            unsigned bf[4][2];
#pragma unroll
            for (int nt = 0; nt < 4; ++nt) {
                const int col = wn * 32 + nt * 8 + g;
                bf[nt][0] = __float_as_uint(Bs[buf][k1][col]);
                bf[nt][1] = __float_as_uint(Bs[buf][k2][col]);
            }
#pragma unroll
            for (int mt = 0; mt < 4; ++mt)
#pragma unroll
                for (int nt = 0; nt < 4; ++nt) MMA_TF32(acc[mt][nt], af[mt], bf[nt]);
        }
        if (s + 1 < nSt) {
            const int nb = buf ^ 1;
            As[nb][lc + 0][lr] = tf32f(pa0.x); As[nb][lc + 1][lr] = tf32f(pa0.y);
            As[nb][lc + 2][lr] = tf32f(pa0.z); As[nb][lc + 3][lr] = tf32f(pa0.w);
            As[nb][lc + 0][lr + 64] = tf32f(pa1.x); As[nb][lc + 1][lr + 64] = tf32f(pa1.y);
            As[nb][lc + 2][lr + 64] = tf32f(pa1.z); As[nb][lc + 3][lr + 64] = tf32f(pa1.w);
            Bs[nb][lc + 0][lr] = tf32f(pb0.x); Bs[nb][lc + 1][lr] = tf32f(pb0.y);
            Bs[nb][lc + 2][lr] = tf32f(pb0.z); Bs[nb][lc + 3][lr] = tf32f(pb0.w);
            Bs[nb][lc + 0][lr + 64] = tf32f(pb1.x); Bs[nb][lc + 1][lr + 64] = tf32f(pb1.y);
            Bs[nb][lc + 2][lr + 64] = tf32f(pb1.z); Bs[nb][lc + 3][lr + 64] = tf32f(pb1.w);
        }
        __syncthreads();
    }
    epi_tc<EPI>(acc, Cb, ldc, m0, n0, wm, wn, g, tq, epp);
}

// ---------------------------------------------------------------------------
// TN GEMM (tf32 mma): C[m,n] = sum_k A[k*lda+m]*B[k*ldb+n] (M/N-contiguous).
// Same tile/threading; loader stores contiguous m-rows (vectorized, aligned).
// ---------------------------------------------------------------------------
template <int EPI>
__global__ void __launch_bounds__(256) gemm_tc_tn(
    const float* __restrict__ A, int lda, long sAb, long sAh,
    const float* __restrict__ B, int ldb, long sBb, long sBh,
    float* __restrict__ C, int ldc, long sCb, long sCh,
    int K, int Hdiv, const float* __restrict__ ep, long sEpb) {
    __shared__ __align__(16) float As[2][16][132];
    __shared__ __align__(16) float Bs[2][16][132];
    const int z = blockIdx.z;
    const int b = z / Hdiv, h = z - b * Hdiv;
    const float* Ab = A + (long)b * sAb + (long)h * sAh;
    const float* Bb = B + (long)b * sBb + (long)h * sBh;
    float* Cb = C + (long)b * sCb + (long)h * sCh;
    const float* epp = ep ? (ep + (long)b * sEpb) : ep;

    const int m0 = blockIdx.y << 7;
    const int n0 = blockIdx.x << 7;
    const int tid = threadIdx.x;
    const int warp = tid >> 5, lane = tid & 31;
    const int wm = warp & 1, wn = warp >> 1;
    const int g = lane >> 2, tq = lane & 3;

    const int kr = tid >> 4;         // 0..15 (k row)
    const int mc = (tid & 15) << 3;  // 0..120 (m offset, 8 floats)
    const float* ApT = Ab + (long)kr * lda + m0 + mc;
    const float* BpT = Bb + (long)kr * ldb + n0 + mc;

    float4 qa0 = *reinterpret_cast<const float4*>(ApT);
    float4 qa1 = *reinterpret_cast<const float4*>(ApT + 4);
    float4 qb0 = *reinterpret_cast<const float4*>(BpT);
    float4 qb1 = *reinterpret_cast<const float4*>(BpT + 4);

    {
        *reinterpret_cast<float4*>(&As[0][kr][mc]) =
            make_float4(tf32f(qa0.x), tf32f(qa0.y), tf32f(qa0.z), tf32f(qa0.w));
        *reinterpret_cast<float4*>(&As[0][kr][mc + 4]) =
            make_float4(tf32f(qa1.x), tf32f(qa1.y), tf32f(qa1.z), tf32f(qa1.w));
        *reinterpret_cast<float4*>(&Bs[0][kr][mc]) =
            make_float4(tf32f(qb0.x), tf32f(qb0.y), tf32f(qb0.z), tf32f(qb0.w));
        *reinterpret_cast<float4*>(&Bs[0][kr][mc + 4]) =
            make_float4(tf32f(qb1.x), tf32f(qb1.y), tf32f(qb1.z), tf32f(qb1.w));
    }
    __syncthreads();

    float acc[4][4][4] = {};
    const int nSt = K >> 4;
    for (int s = 0; s < nSt; ++s) {
        const int buf = s & 1;
        if (s + 1 < nSt) {
            const long k0 = (long)((s + 1) << 4);
            qa0 = *reinterpret_cast<const float4*>(ApT + k0 * lda);
            qa1 = *reinterpret_cast<const float4*>(ApT + k0 * lda + 4);
            qb0 = *reinterpret_cast<const float4*>(BpT + k0 * ldb);
            qb1 = *reinterpret_cast<const float4*>(BpT + k0 * ldb + 4);
        }
#pragma unroll
        for (int kb = 0; kb < 2; ++kb) {
            const int k1 = kb * 8 + tq, k2 = k1 + 4;
            unsigned af[4][4];
#pragma unroll
            for (int mt = 0; mt < 4; ++mt) {
                const int row = wm * 64 + mt * 16 + g;
                af[mt][0] = __float_as_uint(As[buf][k1][row]);
                af[mt][1] = __float_as_uint(As[buf][k1][row + 8]);
                af[mt][2] = __float_as_uint(As[buf][k2][row]);
                af[mt][3] = __float_as_uint(As[buf][k2][row + 8]);
            }
            unsigned bf[4][2];
#pragma unroll
            for (int nt = 0; nt < 4; ++nt) {
                const int col = wn * 32 + nt * 8 + g;
                bf[nt][0] = __float_as_uint(Bs[buf][k1][col]);
                bf[nt][1] = __float_as_uint(Bs[buf][k2][col]);
            }
#pragma unroll
            for (int mt = 0; mt < 4; ++mt)
#pragma unroll
                for (int nt = 0; nt < 4; ++nt) MMA_TF32(acc[mt][nt], af[mt], bf[nt]);
        }
        if (s + 1 < nSt) {
            const int nb = buf ^ 1;
            *reinterpret_cast<float4*>(&As[nb][kr][mc]) =
                make_float4(tf32f(qa0.x), tf32f(qa0.y), tf32f(qa0.z), tf32f(qa0.w));
            *reinterpret_cast<float4*>(&As[nb][kr][mc + 4]) =
                make_float4(tf32f(qa1.x), tf32f(qa1.y), tf32f(qa1.z), tf32f(qa1.w));
            *reinterpret_cast<float4*>(&Bs[nb][kr][mc]) =
                make_float4(tf32f(qb0.x), tf32f(qb0.y), tf32f(qb0.z), tf32f(qb0.w));
            *reinterpret_cast<float4*>(&Bs[nb][kr][mc + 4]) =
                make_float4(tf32f(qb1.x), tf32f(qb1.y), tf32f(qb1.z), tf32f(qb1.w));
        }
        __syncthreads();
    }
    epi_tc<EPI>(acc, Cb, ldc, m0, n0, wm, wn, g, tq, epp);
}

// ---------------------------------------------------------------------------
// LayerNorm over last dim (512). One warp per row, float4 vectorized.
// ---------------------------------------------------------------------------
__global__ void __launch_bounds__(256) ln_kernel(
    const float* __restrict__ in, float* __restrict__ out,
    const float* __restrict__ gamma, const float* __restrict__ beta, float eps) {
    const int warp = blockIdx.x * (blockDim.x >> 5) + (threadIdx.x >> 5);
    const int lane = threadIdx.x & 31;
    const float4* r = reinterpret_cast<const float4*>(in + (long)warp * 512);
    float4 v[4];
    float s = 0.f, s2 = 0.f;
#pragma unroll
    for (int i = 0; i < 4; ++i) {
        v[i] = r[lane + (i << 5)];
        s  += v[i].x + v[i].y + v[i].z + v[i].w;
        s2 += v[i].x * v[i].x + v[i].y * v[i].y + v[i].z * v[i].z + v[i].w * v[i].w;
    }
#pragma unroll
    for (int o = 16; o > 0; o >>= 1) {
        s  += __shfl_xor_sync(0xffffffffu, s, o);
        s2 += __shfl_xor_sync(0xffffffffu, s2, o);
    }
    const float mu = s * (1.f / 512.f);
    const float rstd = rsqrtf(s2 * (1.f / 512.f) - mu * mu + eps);
    float4* w = reinterpret_cast<float4*>(out + (long)warp * 512);
#pragma unroll
    for (int i = 0; i < 4; ++i) {
        const float4 g4 = reinterpret_cast<const float4*>(gamma)[lane + (i << 5)];
        const float4 b4 = reinterpret_cast<const float4*>(beta)[lane + (i << 5)];
        float4 o4;
        o4.x = (v[i].x - mu) * rstd * g4.x + b4.x;
        o4.y = (v[i].y - mu) * rstd * g4.y + b4.y;
        o4.z = (v[i].z - mu) * rstd * g4.z + b4.z;
        o4.w = (v[i].w - mu) * rstd * g4.w + b4.w;
        w[lane + (i << 5)] = o4;
    }
}

// ---------------------------------------------------------------------------
// InstanceNorm stats: per (b,h), mean/rstd over 512x512.
// ---------------------------------------------------------------------------
__global__ void __launch_bounds__(256) inorm_stats(const float* __restrict__ sc,
                                                   float* __restrict__ stats) {
    __shared__ float sh[256], sh2[256];
    const int z = blockIdx.x;
    const float4* p = reinterpret_cast<const float4*>(sc + (long)z * 262144);
    float s = 0.f, s2 = 0.f;
    for (int i = threadIdx.x; i < 65536; i += 256) {
        const float4 v = p[i];
        s  += v.x + v.y + v.z + v.w;
        s2 += v.x * v.x + v.y * v.y + v.z * v.z + v.w * v.w;
    }
    sh[threadIdx.x] = s; sh2[threadIdx.x] = s2;
    __syncthreads();
    for (int o = 128; o > 0; o >>= 1) {
        if (threadIdx.x < o) { sh[threadIdx.x] += sh[threadIdx.x + o]; sh2[threadIdx.x] += sh2[threadIdx.x + o]; }
        __syncthreads();
    }
    if (threadIdx.x == 0) {
        const float mu = sh[0] * (1.f / 262144.f);
        const float var = sh2[0] * (1.f / 262144.f) - mu * mu;
        stats[z * 2 + 0] = mu;
        stats[z * 2 + 1] = rsqrtf(var + 1e-5f);
    }
}

// ---------------------------------------------------------------------------
// Fused instance-norm-apply + softmax over rows of 512, in place. One warp/row.
// ---------------------------------------------------------------------------
__global__ void __launch_bounds__(256) softmax_rows(float* __restrict__ sc,
                                                    const float* __restrict__ stats) {
    const int warp = blockIdx.x * (blockDim.x >> 5) + (threadIdx.x >> 5);
    const int lane = threadIdx.x & 31;
    const int z = warp >> 9;
    const float mu = stats[z * 2 + 0];
    const float rstd = stats[z * 2 + 1];
    float4* row = reinterpret_cast<float4*>(sc + (long)warp * 512);
    float4 v[4];
    float mx = -1e30f;
#pragma unroll
    for (int i = 0; i < 4; ++i) {
        v[i] = row[lane + (i << 5)];
        v[i].x = (v[i].x - mu) * rstd; v[i].y = (v[i].y - mu) * rstd;
        v[i].z = (v[i].z - mu) * rstd; v[i].w = (v[i].w - mu) * rstd;
        mx = fmaxf(mx, fmaxf(fmaxf(v[i].x, v[i].y), fmaxf(v[i].z, v[i].w)));
    }
#pragma unroll
    for (int o = 16; o > 0; o >>= 1) mx = fmaxf(mx, __shfl_xor_sync(0xffffffffu, mx, o));
    float s = 0.f;
#pragma unroll
    for (int i = 0; i < 4; ++i) {
        v[i].x = __expf(v[i].x - mx); v[i].y = __expf(v[i].y - mx);
        v[i].z = __expf(v[i].z - mx); v[i].w = __expf(v[i].w - mx);
        s += v[i].x + v[i].y + v[i].z + v[i].w;
    }
#pragma unroll
    for (int o = 16; o > 0; o >>= 1) s += __shfl_xor_sync(0xffffffffu, s, o);
    const float inv = 1.f / s;
#pragma unroll
    for (int i = 0; i < 4; ++i) {
        v[i].x *= inv; v[i].y *= inv; v[i].z *= inv; v[i].w *= inv;
        row[lane + (i << 5)] = v[i];
    }
}

// ---------------------------------------------------------------------------
// Weight pre-processing
// ---------------------------------------------------------------------------
__global__ void __launch_bounds__(256) transpose_rc(const float* __restrict__ in,
                                                    float* __restrict__ out,
                                                    int rows, int cols) {
    __shared__ float t[32][33];
    const int c0 = blockIdx.x << 5, r0 = blockIdx.y << 5;
    const int tx = threadIdx.x, ty = threadIdx.y;  // 32 x 8
#pragma unroll
    for (int j = 0; j < 32; j += 8) t[ty + j][tx] = in[(long)(r0 + ty + j) * cols + c0 + tx];
    __syncthreads();
#pragma unroll
    for (int j = 0; j < 32; j += 8) out[(long)(c0 + ty + j) * rows + r0 + tx] = t[tx][ty + j];
}

__global__ void __launch_bounds__(256) permute_wo(const float* __restrict__ wo,
                                                  float* __restrict__ woT) {
    // woT[o*4096 + h*512 + c] = wo[(c*8+h)*512 + o]
    const long idx = (long)blockIdx.x * 256 + threadIdx.x;  // over 512*4096
    const int o = (int)(idx & 511);
    const int ch = (int)(idx >> 9);
    const int h = ch & 7;
    const int c = ch >> 3;
    woT[(long)o * 4096 + h * 512 + c] = wo[idx];
}

// ---------------------------------------------------------------------------
// Host launcher
// ---------------------------------------------------------------------------
extern "C" void kernel_launch(void* const* d_in, const int* in_sizes, int n_in,
                              void* d_out, int out_size) {
    const float* x      = (const float*)d_in[0];
    const float* proj_w = (const float*)d_in[1];
    const float* proj_b = (const float*)d_in[2];
    const float* ln1_g  = (const float*)d_in[3];
    const float* ln1_b  = (const float*)d_in[4];
    const float* wq     = (const float*)d_in[5];
    const float* wk     = (const float*)d_in[6];
    const float* wv     = (const float*)d_in[7];
    const float* wo     = (const float*)d_in[8];
    const float* ln2_g  = (const float*)d_in[9];
    const float* ln2_b  = (const float*)d_in[10];
    const float* mo_w   = (const float*)d_in[11];
    const float* mo_b   = (const float*)d_in[12];
    float* out = (float*)d_out;

    float *emb, *xn, *q, *k, *v, *sc, *ob, *st, *wqT, *wkT, *wvT, *woT;
    cudaGetSymbolAddress((void**)&emb, g_emb);
    cudaGetSymbolAddress((void**)&xn,  g_xn);
    cudaGetSymbolAddress((void**)&q,   g_q);
    cudaGetSymbolAddress((void**)&k,   g_k);
    cudaGetSymbolAddress((void**)&v,   g_v);
    cudaGetSymbolAddress((void**)&sc,  g_sc);
    cudaGetSymbolAddress((void**)&ob,  g_ob);
    cudaGetSymbolAddress((void**)&st,  g_st);
    cudaGetSymbolAddress((void**)&wqT, g_wqT);
    cudaGetSymbolAddress((void**)&wkT, g_wkT);
    cudaGetSymbolAddress((void**)&wvT, g_wvT);
    cudaGetSymbolAddress((void**)&woT, g_woT);

    // Weight prep
    transpose_rc<<<dim3(128, 16), dim3(32, 8)>>>(wq, wqT, 512, 4096);
    transpose_rc<<<dim3(128, 16), dim3(32, 8)>>>(wk, wkT, 512, 4096);
    transpose_rc<<<dim3(128, 16), dim3(32, 8)>>>(wv, wvT, 512, 4096);
    permute_wo<<<8192, 256>>>(wo, woT);

    // 1) Patch embed: emb[b,n,c] = sum_p proj_w[n,p]*x[b,c,p] + proj_b[n]
    //    M=256, N=512, K=256
    gemm_tc_nt<1><<<dim3(4, 2, 32), 256>>>(proj_w, 256, 0, 0,
                                           x, 256, 131072L, 0,
                                           emb, 512, 131072L, 0,
                                           256, 1, proj_b, 0);
    // 2) LN1
    ln_kernel<<<1024, 256>>>(emb, xn, ln1_g, ln1_b, 1e-6f);
    // 3) Q,K,V: M=256, N=4096, K=512 per batch
    gemm_tc_nt<0><<<dim3(32, 2, 32), 256>>>(xn, 512, 131072L, 0, wqT, 512, 0, 0,
                                            q, 4096, 1048576L, 0, 512, 1, nullptr, 0);
    gemm_tc_nt<0><<<dim3(32, 2, 32), 256>>>(xn, 512, 131072L, 0, wkT, 512, 0, 0,
                                            k, 4096, 1048576L, 0, 512, 1, nullptr, 0);
    gemm_tc_nt<0><<<dim3(32, 2, 32), 256>>>(xn, 512, 131072L, 0, wvT, 512, 0, 0,
                                            v, 4096, 1048576L, 0, 512, 1, nullptr, 0);
    // 4) Scores: per (b,h) M=512, N=512, K=256 (TN)
    gemm_tc_tn<0><<<dim3(4, 4, 256), 256>>>(q, 4096, 1048576L, 512, k, 4096, 1048576L, 512,
                                            sc, 512, 2097152L, 262144L, 256, 8, nullptr, 0);
    // 5) InstanceNorm stats + fused normalize+softmax (in place)
    inorm_stats<<<256, 256>>>(sc, st);
    softmax_rows<<<16384, 256>>>(sc, st);
    // 6) ctx2[b,n,h,i] = sum_j v[b,n,h,j]*attn[b,h,i,j]: M=256, N=512, K=512 per (b,h)
    gemm_tc_nt<0><<<dim3(4, 2, 256), 256>>>(v, 4096, 1048576L, 512, sc, 512, 2097152L, 262144L,
                                            q, 4096, 1048576L, 512, 512, 8, nullptr, 0);
    // 7) Out-proj + residual: M=256, N=512, K=4096
    gemm_tc_nt<2><<<dim3(4, 2, 32), 256>>>(q, 4096, 1048576L, 0, woT, 4096, 0, 0,
                                           ob, 512, 131072L, 0, 4096, 1, emb, 131072L);
    // 8) LN2 (reuse g_xn)
    ln_kernel<<<1024, 256>>>(ob, xn, ln2_g, ln2_b, 1e-6f);
    // 9) 1x1 conv + bias + exact GELU, direct to d_out: M=512, N=256, K=512
    gemm_tc_nt<3><<<dim3(2, 4, 32), 256>>>(mo_w, 512, 0, 0, xn, 512, 131072L, 0,
                                           out, 256, 131072L, 0, 512, 1, mo_b, 0);
}

// round 5
// speedup vs baseline: 3.7740x; 1.1561x over previous
#include <cuda_runtime.h>
#include <math.h>

// ---------------------------------------------------------------------------
// Problem constants (batch already halved: cat(x,x) duplicates, out[:b] keeps half)
//   B=32, C=512, N=256 (seq), H=8, P=256 (patch flat), HC=4096
// ---------------------------------------------------------------------------

__device__ float g_emb[32 * 256 * 512];      //  (b, n, c)
__device__ float g_xn [32 * 256 * 512];      //  LN outputs (reused for LN2 output)
__device__ float g_q  [32 * 256 * 4096];     //  (b, n, h*512+i); reused for ctx2
__device__ float g_k  [32 * 256 * 4096];
__device__ float g_v  [32 * 256 * 4096];
__device__ float g_sc [32 * 8 * 512 * 512];  //  scores -> attn in place
__device__ float g_ob [32 * 256 * 512];      //  out-proj + residual
__device__ float g_st [32 * 8 * 2];          //  instance-norm mean/rstd
__device__ float g_wqT[4096 * 512];
__device__ float g_wkT[4096 * 512];
__device__ float g_wvT[4096 * 512];
__device__ float g_woT[512 * 4096];          //  woT[o,h*512+c] = wo[c*8+h, o]

__device__ __forceinline__ float gelu_f(float x) {
    return 0.5f * x * (1.0f + erff(x * 0.70710678118654752f));
}

__device__ __forceinline__ float tf32f(float f) {
    unsigned u;
    asm("cvt.rna.tf32.f32 %0, %1;" : "=r"(u) : "f"(f));
    return __uint_as_float(u);
}

#define MMA_TF32(c, a, b)                                                     \
    asm volatile(                                                             \
        "mma.sync.aligned.m16n8k8.row.col.f32.tf32.tf32.f32 "                 \
        "{%0,%1,%2,%3},{%4,%5,%6,%7},{%8,%9},{%0,%1,%2,%3};"                  \
        : "+f"(c[0]), "+f"(c[1]), "+f"(c[2]), "+f"(c[3])                      \
        : "r"(a[0]), "r"(a[1]), "r"(a[2]), "r"(a[3]), "r"(b[0]), "r"(b[1]))

// ---------------------------------------------------------------------------
// Epilogue (scalar stores). Thread owns acc[4][8][4] of warp tile 64x64.
// EPI: 0 none | 1 +bias[m] | 2 +res[m*ldc+n] | 3 +bias[m] then exact GELU
// ---------------------------------------------------------------------------
template <int EPI>
__device__ __forceinline__ void epi_tc(float acc[4][8][4], float* Cb, int ldc,
                                       int m0, int n0, int wm, int wn, int g, int tq,
                                       const float* __restrict__ epp) {
#pragma unroll
    for (int mt = 0; mt < 4; ++mt) {
        const int r1 = m0 + wm * 64 + mt * 16 + g;
        const int r2 = r1 + 8;
        float b1 = 0.f, b2 = 0.f;
        if (EPI == 1 || EPI == 3) { b1 = epp[r1]; b2 = epp[r2]; }
#pragma unroll
        for (int nt = 0; nt < 8; ++nt) {
            const int col = n0 + wn * 64 + nt * 8 + 2 * tq;
            float c0 = acc[mt][nt][0], c1 = acc[mt][nt][1];
            float c2 = acc[mt][nt][2], c3 = acc[mt][nt][3];
            if (EPI == 1 || EPI == 3) { c0 += b1; c1 += b1; c2 += b2; c3 += b2; }
            if (EPI == 2) {
                c0 += epp[(long)r1 * ldc + col];
                c1 += epp[(long)r1 * ldc + col + 1];
                c2 += epp[(long)r2 * ldc + col];
                c3 += epp[(long)r2 * ldc + col + 1];
            }
            if (EPI == 3) {
                c0 = gelu_f(c0); c1 = gelu_f(c1); c2 = gelu_f(c2); c3 = gelu_f(c3);
            }
            Cb[(long)r1 * ldc + col] = c0;
            Cb[(long)r1 * ldc + col + 1] = c1;
            Cb[(long)r2 * ldc + col] = c2;
            Cb[(long)r2 * ldc + col + 1] = c3;
        }
    }
}

// ---------------------------------------------------------------------------
// NT GEMM (tf32 mma): C[m,n] = sum_k A[m,k]*B[n,k], K-contiguous operands.
// Tile 128x128, BK=16, 128 threads (4 warps as 2m x 2n, warp tile 64x64).
// Smem: plain k-major float [16][132]. M,N % 128 == 0, K % 16 == 0.
// ---------------------------------------------------------------------------
template <int EPI>
__global__ void __launch_bounds__(128, 2) gemm_tc_nt(
    const float* __restrict__ A, int lda, long sAb, long sAh,
    const float* __restrict__ B, int ldb, long sBb, long sBh,
    float* __restrict__ C, int ldc, long sCb, long sCh,
    int K, int Hdiv, const float* __restrict__ ep, long sEpb) {
    __shared__ __align__(16) float As[2][16][132];
    __shared__ __align__(16) float Bs[2][16][132];
    const int z = blockIdx.z;
    const int b = z / Hdiv, h = z - b * Hdiv;
    const float* Ab = A + (long)b * sAb + (long)h * sAh;
    const float* Bb = B + (long)b * sBb + (long)h * sBh;
    float* Cb = C + (long)b * sCb + (long)h * sCh;
    const float* epp = ep ? (ep + (long)b * sEpb) : ep;

    const int m0 = blockIdx.y << 7;
    const int n0 = blockIdx.x << 7;
    const int tid = threadIdx.x;
    const int warp = tid >> 5, lane = tid & 31;
    const int wm = warp & 1, wn = warp >> 1;   // 2m x 2n
    const int g = lane >> 2, tq = lane & 3;

    // Loader: lr = base row (0..31, covers +32i), lc = k offset (float4).
    const int lr = tid >> 2;
    const int lc = (tid & 3) << 2;
    const float* Ap0 = Ab + (long)(m0 + lr) * lda + lc;
    const float* Ap1 = Ap0 + 32L * lda;
    const float* Ap2 = Ap0 + 64L * lda;
    const float* Ap3 = Ap0 + 96L * lda;
    const float* Bp0 = Bb + (long)(n0 + lr) * ldb + lc;
    const float* Bp1 = Bp0 + 32L * ldb;
    const float* Bp2 = Bp0 + 64L * ldb;
    const float* Bp3 = Bp0 + 96L * ldb;

    float4 pa0 = *reinterpret_cast<const float4*>(Ap0);
    float4 pa1 = *reinterpret_cast<const float4*>(Ap1);
    float4 pa2 = *reinterpret_cast<const float4*>(Ap2);
    float4 pa3 = *reinterpret_cast<const float4*>(Ap3);
    float4 pb0 = *reinterpret_cast<const float4*>(Bp0);
    float4 pb1 = *reinterpret_cast<const float4*>(Bp1);
    float4 pb2 = *reinterpret_cast<const float4*>(Bp2);
    float4 pb3 = *reinterpret_cast<const float4*>(Bp3);

#define STS_NT(s)                                                              \
    {                                                                          \
        As[s][lc + 0][lr]      = tf32f(pa0.x); As[s][lc + 1][lr]      = tf32f(pa0.y); \
        As[s][lc + 2][lr]      = tf32f(pa0.z); As[s][lc + 3][lr]      = tf32f(pa0.w); \
        As[s][lc + 0][lr + 32] = tf32f(pa1.x); As[s][lc + 1][lr + 32] = tf32f(pa1.y); \
        As[s][lc + 2][lr + 32] = tf32f(pa1.z); As[s][lc + 3][lr + 32] = tf32f(pa1.w); \
        As[s][lc + 0][lr + 64] = tf32f(pa2.x); As[s][lc + 1][lr + 64] = tf32f(pa2.y); \
        As[s][lc + 2][lr + 64] = tf32f(pa2.z); As[s][lc + 3][lr + 64] = tf32f(pa2.w); \
        As[s][lc + 0][lr + 96] = tf32f(pa3.x); As[s][lc + 1][lr + 96] = tf32f(pa3.y); \
        As[s][lc + 2][lr + 96] = tf32f(pa3.z); As[s][lc + 3][lr + 96] = tf32f(pa3.w); \
        Bs[s][lc + 0][lr]      = tf32f(pb0.x); Bs[s][lc + 1][lr]      = tf32f(pb0.y); \
        Bs[s][lc + 2][lr]      = tf32f(pb0.z); Bs[s][lc + 3][lr]      = tf32f(pb0.w); \
        Bs[s][lc + 0][lr + 32] = tf32f(pb1.x); Bs[s][lc + 1][lr + 32] = tf32f(pb1.y); \
        Bs[s][lc + 2][lr + 32] = tf32f(pb1.z); Bs[s][lc + 3][lr + 32] = tf32f(pb1.w); \
        Bs[s][lc + 0][lr + 64] = tf32f(pb2.x); Bs[s][lc + 1][lr + 64] = tf32f(pb2.y); \
        Bs[s][lc + 2][lr + 64] = tf32f(pb2.z); Bs[s][lc + 3][lr + 64] = tf32f(pb2.w); \
        Bs[s][lc + 0][lr + 96] = tf32f(pb3.x); Bs[s][lc + 1][lr + 96] = tf32f(pb3.y); \
        Bs[s][lc + 2][lr + 96] = tf32f(pb3.z); Bs[s][lc + 3][lr + 96] = tf32f(pb3.w); \
    }

    STS_NT(0);
    __syncthreads();

    float acc[4][8][4] = {};
    const int nSt = K >> 4;
    for (int s = 0; s < nSt; ++s) {
        const int buf = s & 1;
        if (s + 1 < nSt) {
            const int k0 = (s + 1) << 4;
            pa0 = *reinterpret_cast<const float4*>(Ap0 + k0);
            pa1 = *reinterpret_cast<const float4*>(Ap1 + k0);
            pa2 = *reinterpret_cast<const float4*>(Ap2 + k0);
            pa3 = *reinterpret_cast<const float4*>(Ap3 + k0);
            pb0 = *reinterpret_cast<const float4*>(Bp0 + k0);
            pb1 = *reinterpret_cast<const float4*>(Bp1 + k0);
            pb2 = *reinterpret_cast<const float4*>(Bp2 + k0);
            pb3 = *reinterpret_cast<const float4*>(Bp3 + k0);
        }
#pragma unroll
        for (int kb = 0; kb < 2; ++kb) {
            const int k1 = kb * 8 + tq, k2 = k1 + 4;
            unsigned af[4][4];
#pragma unroll
            for (int mt = 0; mt < 4; ++mt) {
                const int row = wm * 64 + mt * 16 + g;
                af[mt][0] = __float_as_uint(As[buf][k1][row]);
                af[mt][1] = __float_as_uint(As[buf][k1][row + 8]);
                af[mt][2] = __float_as_uint(As[buf][k2][row]);
                af[mt][3] = __float_as_uint(As[buf][k2][row + 8]);
            }
            unsigned bf[8][2];
#pragma unroll
            for (int nt = 0; nt < 8; ++nt) {
                const int col = wn * 64 + nt * 8 + g;
                bf[nt][0] = __float_as_uint(Bs[buf][k1][col]);
                bf[nt][1] = __float_as_uint(Bs[buf][k2][col]);
            }
#pragma unroll
            for (int mt = 0; mt < 4; ++mt)
#pragma unroll
                for (int nt = 0; nt < 8; ++nt) MMA_TF32(acc[mt][nt], af[mt], bf[nt]);
        }
        if (s + 1 < nSt) {
            const int nb = buf ^ 1;
            STS_NT(nb);
        }
        __syncthreads();
    }
#undef STS_NT
    epi_tc<EPI>(acc, Cb, ldc, m0, n0, wm, wn, g, tq, epp);
}

// ---------------------------------------------------------------------------
// TN GEMM (tf32 mma): C[m,n] = sum_k A[k*lda+m]*B[k*ldb+n] (M/N-contiguous).
// Same tile/threading; loader stores contiguous m-rows (vectorized, aligned).
// ---------------------------------------------------------------------------
template <int EPI>
__global__ void __launch_bounds__(128, 2) gemm_tc_tn(
    const float* __restrict__ A, int lda, long sAb, long sAh,
    const float* __restrict__ B, int ldb, long sBb, long sBh,
    float* __restrict__ C, int ldc, long sCb, long sCh,
    int K, int Hdiv, const float* __restrict__ ep, long sEpb) {
    __shared__ __align__(16) float As[2][16][132];
    __shared__ __align__(16) float Bs[2][16][132];
    const int z = blockIdx.z;
    const int b = z / Hdiv, h = z - b * Hdiv;
    const float* Ab = A + (long)b * sAb + (long)h * sAh;
    const float* Bb = B + (long)b * sBb + (long)h * sBh;
    float* Cb = C + (long)b * sCb + (long)h * sCh;
    const float* epp = ep ? (ep + (long)b * sEpb) : ep;

    const int m0 = blockIdx.y << 7;
    const int n0 = blockIdx.x << 7;
    const int tid = threadIdx.x;
    const int warp = tid >> 5, lane = tid & 31;
    const int wm = warp & 1, wn = warp >> 1;
    const int g = lane >> 2, tq = lane & 3;

    const int kr = tid >> 3;         // 0..15 (k row)
    const int mc = (tid & 7) << 4;   // 0..112 (m offset, 16 floats)
    const float* ApT = Ab + (long)kr * lda + m0 + mc;
    const float* BpT = Bb + (long)kr * ldb + n0 + mc;

    float4 qa0 = *reinterpret_cast<const float4*>(ApT);
    float4 qa1 = *reinterpret_cast<const float4*>(ApT + 4);
    float4 qa2 = *reinterpret_cast<const float4*>(ApT + 8);
    float4 qa3 = *reinterpret_cast<const float4*>(ApT + 12);
    float4 qb0 = *reinterpret_cast<const float4*>(BpT);
    float4 qb1 = *reinterpret_cast<const float4*>(BpT + 4);
    float4 qb2 = *reinterpret_cast<const float4*>(BpT + 8);
    float4 qb3 = *reinterpret_cast<const float4*>(BpT + 12);

#define STS_TN(s)                                                              \
    {                                                                          \
        *reinterpret_cast<float4*>(&As[s][kr][mc]) =                           \
            make_float4(tf32f(qa0.x), tf32f(qa0.y), tf32f(qa0.z), tf32f(qa0.w)); \
        *reinterpret_cast<float4*>(&As[s][kr][mc + 4]) =                       \
            make_float4(tf32f(qa1.x), tf32f(qa1.y), tf32f(qa1.z), tf32f(qa1.w)); \
        *reinterpret_cast<float4*>(&As[s][kr][mc + 8]) =                       \
            make_float4(tf32f(qa2.x), tf32f(qa2.y), tf32f(qa2.z), tf32f(qa2.w)); \
        *reinterpret_cast<float4*>(&As[s][kr][mc + 12]) =                      \
            make_float4(tf32f(qa3.x), tf32f(qa3.y), tf32f(qa3.z), tf32f(qa3.w)); \
        *reinterpret_cast<float4*>(&Bs[s][kr][mc]) =                           \
            make_float4(tf32f(qb0.x), tf32f(qb0.y), tf32f(qb0.z), tf32f(qb0.w)); \
        *reinterpret_cast<float4*>(&Bs[s][kr][mc + 4]) =                       \
            make_float4(tf32f(qb1.x), tf32f(qb1.y), tf32f(qb1.z), tf32f(qb1.w)); \
        *reinterpret_cast<float4*>(&Bs[s][kr][mc + 8]) =                       \
            make_float4(tf32f(qb2.x), tf32f(qb2.y), tf32f(qb2.z), tf32f(qb2.w)); \
        *reinterpret_cast<float4*>(&Bs[s][kr][mc + 12]) =                      \
            make_float4(tf32f(qb3.x), tf32f(qb3.y), tf32f(qb3.z), tf32f(qb3.w)); \
    }

    STS_TN(0);
    __syncthreads();

    float acc[4][8][4] = {};
    const int nSt = K >> 4;
    for (int s = 0; s < nSt; ++s) {
        const int buf = s & 1;
        if (s + 1 < nSt) {
            const long k0 = (long)((s + 1) << 4);
            qa0 = *reinterpret_cast<const float4*>(ApT + k0 * lda);
            qa1 = *reinterpret_cast<const float4*>(ApT + k0 * lda + 4);
            qa2 = *reinterpret_cast<const float4*>(ApT + k0 * lda + 8);
            qa3 = *reinterpret_cast<const float4*>(ApT + k0 * lda + 12);
            qb0 = *reinterpret_cast<const float4*>(BpT + k0 * ldb);
            qb1 = *reinterpret_cast<const float4*>(BpT + k0 * ldb + 4);
            qb2 = *reinterpret_cast<const float4*>(BpT + k0 * ldb + 8);
            qb3 = *reinterpret_cast<const float4*>(BpT + k0 * ldb + 12);
        }
#pragma unroll
        for (int kb = 0; kb < 2; ++kb) {
            const int k1 = kb * 8 + tq, k2 = k1 + 4;
            unsigned af[4][4];
#pragma unroll
            for (int mt = 0; mt < 4; ++mt) {
                const int row = wm * 64 + mt * 16 + g;
                af[mt][0] = __float_as_uint(As[buf][k1][row]);
                af[mt][1] = __float_as_uint(As[buf][k1][row + 8]);
                af[mt][2] = __float_as_uint(As[buf][k2][row]);
                af[mt][3] = __float_as_uint(As[buf][k2][row + 8]);
            }
            unsigned bf[8][2];
#pragma unroll
            for (int nt = 0; nt < 8; ++nt) {
                const int col = wn * 64 + nt * 8 + g;
                bf[nt][0] = __float_as_uint(Bs[buf][k1][col]);
                bf[nt][1] = __float_as_uint(Bs[buf][k2][col]);
            }
#pragma unroll
            for (int mt = 0; mt < 4; ++mt)
#pragma unroll
                for (int nt = 0; nt < 8; ++nt) MMA_TF32(acc[mt][nt], af[mt], bf[nt]);
        }
        if (s + 1 < nSt) {
            const int nb = buf ^ 1;
            STS_TN(nb);
        }
        __syncthreads();
    }
#undef STS_TN
    epi_tc<EPI>(acc, Cb, ldc, m0, n0, wm, wn, g, tq, epp);
}

// ---------------------------------------------------------------------------
// LayerNorm over last dim (512). One warp per row, float4 vectorized.
// ---------------------------------------------------------------------------
__global__ void __launch_bounds__(256) ln_kernel(
    const float* __restrict__ in, float* __restrict__ out,
    const float* __restrict__ gamma, const float* __restrict__ beta, float eps) {
    const int warp = blockIdx.x * (blockDim.x >> 5) + (threadIdx.x >> 5);
    const int lane = threadIdx.x & 31;
    const float4* r = reinterpret_cast<const float4*>(in + (long)warp * 512);
    float4 v[4];
    float s = 0.f, s2 = 0.f;
#pragma unroll
    for (int i = 0; i < 4; ++i) {
        v[i] = r[lane + (i << 5)];
        s  += v[i].x + v[i].y + v[i].z + v[i].w;
        s2 += v[i].x * v[i].x + v[i].y * v[i].y + v[i].z * v[i].z + v[i].w * v[i].w;
    }
#pragma unroll
    for (int o = 16; o > 0; o >>= 1) {
        s  += __shfl_xor_sync(0xffffffffu, s, o);
        s2 += __shfl_xor_sync(0xffffffffu, s2, o);
    }
    const float mu = s * (1.f / 512.f);
    const float rstd = rsqrtf(s2 * (1.f / 512.f) - mu * mu + eps);
    float4* w = reinterpret_cast<float4*>(out + (long)warp * 512);
#pragma unroll
    for (int i = 0; i < 4; ++i) {
        const float4 g4 = reinterpret_cast<const float4*>(gamma)[lane + (i << 5)];
        const float4 b4 = reinterpret_cast<const float4*>(beta)[lane + (i << 5)];
        float4 o4;
        o4.x = (v[i].x - mu) * rstd * g4.x + b4.x;
        o4.y = (v[i].y - mu) * rstd * g4.y + b4.y;
        o4.z = (v[i].z - mu) * rstd * g4.z + b4.z;
        o4.w = (v[i].w - mu) * rstd * g4.w + b4.w;
        w[lane + (i << 5)] = o4;
    }
}

// ---------------------------------------------------------------------------
// InstanceNorm stats: per (b,h), mean/rstd over 512x512.
// ---------------------------------------------------------------------------
__global__ void __launch_bounds__(256) inorm_stats(const float* __restrict__ sc,
                                                   float* __restrict__ stats) {
    __shared__ float sh[256], sh2[256];
    const int z = blockIdx.x;
    const float4* p = reinterpret_cast<const float4*>(sc + (long)z * 262144);
    float s = 0.f, s2 = 0.f;
    for (int i = threadIdx.x; i < 65536; i += 256) {
        const float4 v = p[i];
        s  += v.x + v.y + v.z + v.w;
        s2 += v.x * v.x + v.y * v.y + v.z * v.z + v.w * v.w;
    }
    sh[threadIdx.x] = s; sh2[threadIdx.x] = s2;
    __syncthreads();
    for (int o = 128; o > 0; o >>= 1) {
        if (threadIdx.x < o) { sh[threadIdx.x] += sh[threadIdx.x + o]; sh2[threadIdx.x] += sh2[threadIdx.x + o]; }
        __syncthreads();
    }
    if (threadIdx.x == 0) {
        const float mu = sh[0] * (1.f / 262144.f);
        const float var = sh2[0] * (1.f / 262144.f) - mu * mu;
        stats[z * 2 + 0] = mu;
        stats[z * 2 + 1] = rsqrtf(var + 1e-5f);
    }
}

// ---------------------------------------------------------------------------
// Fused instance-norm-apply + softmax over rows of 512, in place. One warp/row.
// ---------------------------------------------------------------------------
__global__ void __launch_bounds__(256) softmax_rows(float* __restrict__ sc,
                                                    const float* __restrict__ stats) {
    const int warp = blockIdx.x * (blockDim.x >> 5) + (threadIdx.x >> 5);
    const int lane = threadIdx.x & 31;
    const int z = warp >> 9;
    const float mu = stats[z * 2 + 0];
    const float rstd = stats[z * 2 + 1];
    float4* row = reinterpret_cast<float4*>(sc + (long)warp * 512);
    float4 v[4];
    float mx = -1e30f;
#pragma unroll
    for (int i = 0; i < 4; ++i) {
        v[i] = row[lane + (i << 5)];
        v[i].x = (v[i].x - mu) * rstd; v[i].y = (v[i].y - mu) * rstd;
        v[i].z = (v[i].z - mu) * rstd; v[i].w = (v[i].w - mu) * rstd;
        mx = fmaxf(mx, fmaxf(fmaxf(v[i].x, v[i].y), fmaxf(v[i].z, v[i].w)));
    }
#pragma unroll
    for (int o = 16; o > 0; o >>= 1) mx = fmaxf(mx, __shfl_xor_sync(0xffffffffu, mx, o));
    float s = 0.f;
#pragma unroll
    for (int i = 0; i < 4; ++i) {
        v[i].x = __expf(v[i].x - mx); v[i].y = __expf(v[i].y - mx);
        v[i].z = __expf(v[i].z - mx); v[i].w = __expf(v[i].w - mx);
        s += v[i].x + v[i].y + v[i].z + v[i].w;
    }
#pragma unroll
    for (int o = 16; o > 0; o >>= 1) s += __shfl_xor_sync(0xffffffffu, s, o);
    const float inv = 1.f / s;
#pragma unroll
    for (int i = 0; i < 4; ++i) {
        v[i].x *= inv; v[i].y *= inv; v[i].z *= inv; v[i].w *= inv;
        row[lane + (i << 5)] = v[i];
    }
}

// ---------------------------------------------------------------------------
// Weight pre-processing
// ---------------------------------------------------------------------------
__global__ void __launch_bounds__(256) transpose_rc(const float* __restrict__ in,
                                                    float* __restrict__ out,
                                                    int rows, int cols) {
    __shared__ float t[32][33];
    const int c0 = blockIdx.x << 5, r0 = blockIdx.y << 5;
    const int tx = threadIdx.x, ty = threadIdx.y;  // 32 x 8
#pragma unroll
    for (int j = 0; j < 32; j += 8) t[ty + j][tx] = in[(long)(r0 + ty + j) * cols + c0 + tx];
    __syncthreads();
#pragma unroll
    for (int j = 0; j < 32; j += 8) out[(long)(c0 + ty + j) * rows + r0 + tx] = t[tx][ty + j];
}

__global__ void __launch_bounds__(256) permute_wo(const float* __restrict__ wo,
                                                  float* __restrict__ woT) {
    // woT[o*4096 + h*512 + c] = wo[(c*8+h)*512 + o]
    const long idx = (long)blockIdx.x * 256 + threadIdx.x;  // over 512*4096
    const int o = (int)(idx & 511);
    const int ch = (int)(idx >> 9);
    const int h = ch & 7;
    const int c = ch >> 3;
    woT[(long)o * 4096 + h * 512 + c] = wo[idx];
}

// ---------------------------------------------------------------------------
// Host launcher
// ---------------------------------------------------------------------------
extern "C" void kernel_launch(void* const* d_in, const int* in_sizes, int n_in,
                              void* d_out, int out_size) {
    const float* x      = (const float*)d_in[0];
    const float* proj_w = (const float*)d_in[1];
    const float* proj_b = (const float*)d_in[2];
    const float* ln1_g  = (const float*)d_in[3];
    const float* ln1_b  = (const float*)d_in[4];
    const float* wq     = (const float*)d_in[5];
    const float* wk     = (const float*)d_in[6];
    const float* wv     = (const float*)d_in[7];
    const float* wo     = (const float*)d_in[8];
    const float* ln2_g  = (const float*)d_in[9];
    const float* ln2_b  = (const float*)d_in[10];
    const float* mo_w   = (const float*)d_in[11];
    const float* mo_b   = (const float*)d_in[12];
    float* out = (float*)d_out;

    float *emb, *xn, *q, *k, *v, *sc, *ob, *st, *wqT, *wkT, *wvT, *woT;
    cudaGetSymbolAddress((void**)&emb, g_emb);
    cudaGetSymbolAddress((void**)&xn,  g_xn);
    cudaGetSymbolAddress((void**)&q,   g_q);
    cudaGetSymbolAddress((void**)&k,   g_k);
    cudaGetSymbolAddress((void**)&v,   g_v);
    cudaGetSymbolAddress((void**)&sc,  g_sc);
    cudaGetSymbolAddress((void**)&ob,  g_ob);
    cudaGetSymbolAddress((void**)&st,  g_st);
    cudaGetSymbolAddress((void**)&wqT, g_wqT);
    cudaGetSymbolAddress((void**)&wkT, g_wkT);
    cudaGetSymbolAddress((void**)&wvT, g_wvT);
    cudaGetSymbolAddress((void**)&woT, g_woT);

    // Weight prep
    transpose_rc<<<dim3(128, 16), dim3(32, 8)>>>(wq, wqT, 512, 4096);
    transpose_rc<<<dim3(128, 16), dim3(32, 8)>>>(wk, wkT, 512, 4096);
    transpose_rc<<<dim3(128, 16), dim3(32, 8)>>>(wv, wvT, 512, 4096);
    permute_wo<<<8192, 256>>>(wo, woT);

    // 1) Patch embed: emb[b,n,c] = sum_p proj_w[n,p]*x[b,c,p] + proj_b[n]
    //    M=256, N=512, K=256
    gemm_tc_nt<1><<<dim3(4, 2, 32), 128>>>(proj_w, 256, 0, 0,
                                           x, 256, 131072L, 0,
                                           emb, 512, 131072L, 0,
                                           256, 1, proj_b, 0);
    // 2) LN1
    ln_kernel<<<1024, 256>>>(emb, xn, ln1_g, ln1_b, 1e-6f);
    // 3) Q,K,V: M=256, N=4096, K=512 per batch
    gemm_tc_nt<0><<<dim3(32, 2, 32), 128>>>(xn, 512, 131072L, 0, wqT, 512, 0, 0,
                                            q, 4096, 1048576L, 0, 512, 1, nullptr, 0);
    gemm_tc_nt<0><<<dim3(32, 2, 32), 128>>>(xn, 512, 131072L, 0, wkT, 512, 0, 0,
                                            k, 4096, 1048576L, 0, 512, 1, nullptr, 0);
    gemm_tc_nt<0><<<dim3(32, 2, 32), 128>>>(xn, 512, 131072L, 0, wvT, 512, 0, 0,
                                            v, 4096, 1048576L, 0, 512, 1, nullptr, 0);
    // 4) Scores: per (b,h) M=512, N=512, K=256 (TN)
    gemm_tc_tn<0><<<dim3(4, 4, 256), 128>>>(q, 4096, 1048576L, 512, k, 4096, 1048576L, 512,
                                            sc, 512, 2097152L, 262144L, 256, 8, nullptr, 0);
    // 5) InstanceNorm stats + fused normalize+softmax (in place)
    inorm_stats<<<256, 256>>>(sc, st);
    softmax_rows<<<16384, 256>>>(sc, st);
    // 6) ctx2[b,n,h,i] = sum_j v[b,n,h,j]*attn[b,h,i,j]: M=256, N=512, K=512 per (b,h)
    gemm_tc_nt<0><<<dim3(4, 2, 256), 128>>>(v, 4096, 1048576L, 512, sc, 512, 2097152L, 262144L,
                                            q, 4096, 1048576L, 512, 512, 8, nullptr, 0);
    // 7) Out-proj + residual: M=256, N=512, K=4096
    gemm_tc_nt<2><<<dim3(4, 2, 32), 128>>>(q, 4096, 1048576L, 0, woT, 4096, 0, 0,
                                           ob, 512, 131072L, 0, 4096, 1, emb, 131072L);
    // 8) LN2 (reuse g_xn)
    ln_kernel<<<1024, 256>>>(ob, xn, ln2_g, ln2_b, 1e-6f);
    // 9) 1x1 conv + bias + exact GELU, direct to d_out: M=512, N=256, K=512
    gemm_tc_nt<3><<<dim3(2, 4, 32), 128>>>(mo_w, 512, 0, 0, xn, 512, 131072L, 0,
                                           out, 256, 131072L, 0, 512, 1, mo_b, 0);
}

// round 7
// speedup vs baseline: 5.0830x; 1.3468x over previous
#include <cuda_runtime.h>
#include <cuda_fp16.h>
#include <math.h>
#include <stdint.h>

// ---------------------------------------------------------------------------
// Problem constants (batch already halved: cat(x,x) duplicates, out[:b] keeps half)
//   B=32, C=512, N=256 (seq), H=8, P=256 (patch flat), HC=4096
// ---------------------------------------------------------------------------

__device__ float g_emb[32 * 256 * 512];      //  (b, n, c)
__device__ float g_xn [32 * 256 * 512];      //  LN outputs (reused for LN2 output)
__device__ float g_q  [32 * 256 * 4096];     //  (b, n, h*512+i); reused for ctx2
__device__ float g_k  [32 * 256 * 4096];
__device__ float g_v  [32 * 256 * 4096];
__device__ float g_sc [32 * 8 * 512 * 512];  //  scores -> attn in place
__device__ float g_ob [32 * 256 * 512];      //  out-proj + residual
__device__ float g_st [32 * 8 * 2];          //  instance-norm mean/rstd
__device__ __half g_wqTh[4096 * 512];        //  half weights (pre-converted)
__device__ __half g_wkTh[4096 * 512];
__device__ __half g_wvTh[4096 * 512];
__device__ __half g_woTh[512 * 4096];        //  woTh[o, h*512+c] = wo[c*8+h, o]

__device__ __forceinline__ float gelu_f(float x) {
    return 0.5f * x * (1.0f + erff(x * 0.70710678118654752f));
}

__device__ __forceinline__ float tf32f(float f) {
    unsigned u;
    asm("cvt.rna.tf32.f32 %0, %1;" : "=r"(u) : "f"(f));
    return __uint_as_float(u);
}

// fp16 MMA, fp32 accumulate: m16n8k16.
#define MMA_F16(c, a, b)                                                      \
    asm volatile(                                                             \
        "mma.sync.aligned.m16n8k16.row.col.f32.f16.f16.f32 "                  \
        "{%0,%1,%2,%3},{%4,%5,%6,%7},{%8,%9},{%0,%1,%2,%3};"                  \
        : "+f"(c[0]), "+f"(c[1]), "+f"(c[2]), "+f"(c[3])                      \
        : "r"(a[0]), "r"(a[1]), "r"(a[2]), "r"(a[3]), "r"(b[0]), "r"(b[1]))

#define MMA_TF32(c, a, b)                                                     \
    asm volatile(                                                             \
        "mma.sync.aligned.m16n8k8.row.col.f32.tf32.tf32.f32 "                 \
        "{%0,%1,%2,%3},{%4,%5,%6,%7},{%8,%9},{%0,%1,%2,%3};"                  \
        : "+f"(c[0]), "+f"(c[1]), "+f"(c[2]), "+f"(c[3])                      \
        : "r"(a[0]), "r"(a[1]), "r"(a[2]), "r"(a[3]), "r"(b[0]), "r"(b[1]))

__device__ __forceinline__ unsigned packh2(float a, float b) {
    const __half2 h = __floats2half2_rn(a, b);
    return *reinterpret_cast<const unsigned*>(&h);
}

// ---------------------------------------------------------------------------
// Epilogue (scalar stores). Thread owns acc[4][8][4] of warp tile 64x64.
// EPI: 0 none | 1 +bias[m] | 2 +res[m*ldc+n] | 3 +bias[m] then exact GELU
// ---------------------------------------------------------------------------
template <int EPI>
__device__ __forceinline__ void epi_tc(float acc[4][8][4], float* Cb, int ldc,
                                       int m0, int n0, int wm, int wn, int g, int tq,
                                       const float* __restrict__ epp) {
#pragma unroll
    for (int mt = 0; mt < 4; ++mt) {
        const int r1 = m0 + wm * 64 + mt * 16 + g;
        const int r2 = r1 + 8;
        float b1 = 0.f, b2 = 0.f;
        if (EPI == 1 || EPI == 3) { b1 = epp[r1]; b2 = epp[r2]; }
#pragma unroll
        for (int nt = 0; nt < 8; ++nt) {
            const int col = n0 + wn * 64 + nt * 8 + 2 * tq;
            float c0 = acc[mt][nt][0], c1 = acc[mt][nt][1];
            float c2 = acc[mt][nt][2], c3 = acc[mt][nt][3];
            if (EPI == 1 || EPI == 3) { c0 += b1; c1 += b1; c2 += b2; c3 += b2; }
            if (EPI == 2) {
                c0 += epp[(long)r1 * ldc + col];
                c1 += epp[(long)r1 * ldc + col + 1];
                c2 += epp[(long)r2 * ldc + col];
                c3 += epp[(long)r2 * ldc + col + 1];
            }
            if (EPI == 3) {
                c0 = gelu_f(c0); c1 = gelu_f(c1); c2 = gelu_f(c2); c3 = gelu_f(c3);
            }
            Cb[(long)r1 * ldc + col] = c0;
            Cb[(long)r1 * ldc + col + 1] = c1;
            Cb[(long)r2 * ldc + col] = c2;
            Cb[(long)r2 * ldc + col + 1] = c3;
        }
    }
}

// ---------------------------------------------------------------------------
// fp16 NT GEMM: C[m,n] = sum_k A[m,k]*B[n,k], K-contiguous operands.
// Tile 128x128, BK=16, 128 threads (4 warps 2x2, warp tile 64x64).
// A fp32 (converted in loader); B fp32 (BH=0) or pre-converted half (BH=1).
// Smem: __half [128][24] per buf (pad 24 -> conflict-free fragment LDS).
// M,N % 128 == 0, K % 16 == 0.
// ---------------------------------------------------------------------------
template <int EPI, int BH>
__global__ void __launch_bounds__(128, 2) gemm_h_nt(
    const float* __restrict__ A, int lda, long sAb, long sAh,
    const void* __restrict__ Bv, int ldb, long sBb, long sBh,
    float* __restrict__ C, int ldc, long sCb, long sCh,
    int K, int Hdiv, const float* __restrict__ ep, long sEpb) {
    __shared__ __align__(16) __half As[2][128][24];
    __shared__ __align__(16) __half Bs[2][128][24];
    const int z = blockIdx.z;
    const int b = z / Hdiv, h = z - b * Hdiv;
    const float* Ab = A + (long)b * sAb + (long)h * sAh;
    const float* Bf = BH ? nullptr : ((const float*)Bv + (long)b * sBb + (long)h * sBh);
    const __half* Bh = BH ? ((const __half*)Bv + (long)b * sBb + (long)h * sBh) : nullptr;
    float* Cb = C + (long)b * sCb + (long)h * sCh;
    const float* epp = ep ? (ep + (long)b * sEpb) : ep;

    const int m0 = blockIdx.y << 7;
    const int n0 = blockIdx.x << 7;
    const int tid = threadIdx.x;
    const int warp = tid >> 5, lane = tid & 31;
    const int wm = warp & 1, wn = warp >> 1;   // 2m x 2n
    const int g = lane >> 2, tq = lane & 3;

    // Loader: rg = base row (0..31, +32p), cp4 = k offset (4 elements).
    const int rg = tid >> 2;
    const int cp4 = (tid & 3) << 2;

    float4 pa[4];
    float4 pbf[4];
    uint2 pbh[4];

#define LDG_STAGE(k0)                                                          \
    {                                                                          \
        _Pragma("unroll") for (int p = 0; p < 4; ++p) {                        \
            const int row = rg + p * 32;                                       \
            pa[p] = *reinterpret_cast<const float4*>(                          \
                Ab + (long)(m0 + row) * lda + (k0) + cp4);                     \
            if (BH)                                                            \
                pbh[p] = *reinterpret_cast<const uint2*>(                      \
                    Bh + (long)(n0 + row) * ldb + (k0) + cp4);                 \
            else                                                               \
                pbf[p] = *reinterpret_cast<const float4*>(                     \
                    Bf + (long)(n0 + row) * ldb + (k0) + cp4);                 \
        }                                                                      \
    }
#define STS_STAGE(s)                                                           \
    {                                                                          \
        _Pragma("unroll") for (int p = 0; p < 4; ++p) {                        \
            const int row = rg + p * 32;                                       \
            uint2 ua;                                                          \
            ua.x = packh2(pa[p].x, pa[p].y);                                   \
            ua.y = packh2(pa[p].z, pa[p].w);                                   \
            *reinterpret_cast<uint2*>(&As[s][row][cp4]) = ua;                  \
            uint2 ub;                                                          \
            if (BH) ub = pbh[p];                                               \
            else { ub.x = packh2(pbf[p].x, pbf[p].y); ub.y = packh2(pbf[p].z, pbf[p].w); } \
            *reinterpret_cast<uint2*>(&Bs[s][row][cp4]) = ub;                  \
        }                                                                      \
    }

    LDG_STAGE(0);
    STS_STAGE(0);
    __syncthreads();

    float acc[4][8][4] = {};
    const int nSt = K >> 4;
    for (int s = 0; s < nSt; ++s) {
        const int buf = s & 1;
        if (s + 1 < nSt) LDG_STAGE((s + 1) << 4);
        {
            unsigned af[4][4];
#pragma unroll
            for (int mt = 0; mt < 4; ++mt) {
                const int row = wm * 64 + mt * 16 + g;
                af[mt][0] = *reinterpret_cast<const unsigned*>(&As[buf][row][2 * tq]);
                af[mt][1] = *reinterpret_cast<const unsigned*>(&As[buf][row + 8][2 * tq]);
                af[mt][2] = *reinterpret_cast<const unsigned*>(&As[buf][row][2 * tq + 8]);
                af[mt][3] = *reinterpret_cast<const unsigned*>(&As[buf][row + 8][2 * tq + 8]);
            }
            unsigned bf[8][2];
#pragma unroll
            for (int nt = 0; nt < 8; ++nt) {
                const int col = wn * 64 + nt * 8 + g;
                bf[nt][0] = *reinterpret_cast<const unsigned*>(&Bs[buf][col][2 * tq]);
                bf[nt][1] = *reinterpret_cast<const unsigned*>(&Bs[buf][col][2 * tq + 8]);
            }
#pragma unroll
            for (int mt = 0; mt < 4; ++mt)
#pragma unroll
                for (int nt = 0; nt < 8; ++nt) MMA_F16(acc[mt][nt], af[mt], bf[nt]);
        }
        if (s + 1 < nSt) STS_STAGE(buf ^ 1);
        __syncthreads();
    }
#undef LDG_STAGE
#undef STS_STAGE
    epi_tc<EPI>(acc, Cb, ldc, m0, n0, wm, wn, g, tq, epp);
}

// ---------------------------------------------------------------------------
// TN GEMM (tf32 mma): C[m,n] = sum_k A[k*lda+m]*B[k*ldb+n] (M/N-contiguous).
// Tile 128x128, BK=16, 128 threads (4 warps 2x2, warp tile 64x64). (scores)
// ---------------------------------------------------------------------------
__global__ void __launch_bounds__(128, 2) gemm_tc_tn(
    const float* __restrict__ A, int lda, long sAb, long sAh,
    const float* __restrict__ B, int ldb, long sBb, long sBh,
    float* __restrict__ C, int ldc, long sCb, long sCh,
    int K, int Hdiv) {
    __shared__ __align__(16) float As[2][16][132];
    __shared__ __align__(16) float Bs[2][16][132];
    const int z = blockIdx.z;
    const int b = z / Hdiv, h = z - b * Hdiv;
    const float* Ab = A + (long)b * sAb + (long)h * sAh;
    const float* Bb = B + (long)b * sBb + (long)h * sBh;
    float* Cb = C + (long)b * sCb + (long)h * sCh;

    const int m0 = blockIdx.y << 7;
    const int n0 = blockIdx.x << 7;
    const int tid = threadIdx.x;
    const int warp = tid >> 5, lane = tid & 31;
    const int wm = warp & 1, wn = warp >> 1;
    const int g = lane >> 2, tq = lane & 3;

    const int kr = tid >> 3;         // 0..15 (k row)
    const int mc = (tid & 7) << 4;   // 0..112 (m offset, 16 floats)
    const float* ApT = Ab + (long)kr * lda + m0 + mc;
    const float* BpT = Bb + (long)kr * ldb + n0 + mc;

    float4 qa0 = *reinterpret_cast<const float4*>(ApT);
    float4 qa1 = *reinterpret_cast<const float4*>(ApT + 4);
    float4 qa2 = *reinterpret_cast<const float4*>(ApT + 8);
    float4 qa3 = *reinterpret_cast<const float4*>(ApT + 12);
    float4 qb0 = *reinterpret_cast<const float4*>(BpT);
    float4 qb1 = *reinterpret_cast<const float4*>(BpT + 4);
    float4 qb2 = *reinterpret_cast<const float4*>(BpT + 8);
    float4 qb3 = *reinterpret_cast<const float4*>(BpT + 12);

#define STS_TN(s)                                                              \
    {                                                                          \
        *reinterpret_cast<float4*>(&As[s][kr][mc]) =                           \
            make_float4(tf32f(qa0.x), tf32f(qa0.y), tf32f(qa0.z), tf32f(qa0.w)); \
        *reinterpret_cast<float4*>(&As[s][kr][mc + 4]) =                       \
            make_float4(tf32f(qa1.x), tf32f(qa1.y), tf32f(qa1.z), tf32f(qa1.w)); \
        *reinterpret_cast<float4*>(&As[s][kr][mc + 8]) =                       \
            make_float4(tf32f(qa2.x), tf32f(qa2.y), tf32f(qa2.z), tf32f(qa2.w)); \
        *reinterpret_cast<float4*>(&As[s][kr][mc + 12]) =                      \
            make_float4(tf32f(qa3.x), tf32f(qa3.y), tf32f(qa3.z), tf32f(qa3.w)); \
        *reinterpret_cast<float4*>(&Bs[s][kr][mc]) =                           \
            make_float4(tf32f(qb0.x), tf32f(qb0.y), tf32f(qb0.z), tf32f(qb0.w)); \
        *reinterpret_cast<float4*>(&Bs[s][kr][mc + 4]) =                       \
            make_float4(tf32f(qb1.x), tf32f(qb1.y), tf32f(qb1.z), tf32f(qb1.w)); \
        *reinterpret_cast<float4*>(&Bs[s][kr][mc + 8]) =                       \
            make_float4(tf32f(qb2.x), tf32f(qb2.y), tf32f(qb2.z), tf32f(qb2.w)); \
        *reinterpret_cast<float4*>(&Bs[s][kr][mc + 12]) =                      \
            make_float4(tf32f(qb3.x), tf32f(qb3.y), tf32f(qb3.z), tf32f(qb3.w)); \
    }

    STS_TN(0);
    __syncthreads();

    float acc[4][8][4] = {};
    const int nSt = K >> 4;
    for (int s = 0; s < nSt; ++s) {
        const int buf = s & 1;
        if (s + 1 < nSt) {
            const long k0 = (long)((s + 1) << 4);
            qa0 = *reinterpret_cast<const float4*>(ApT + k0 * lda);
            qa1 = *reinterpret_cast<const float4*>(ApT + k0 * lda + 4);
            qa2 = *reinterpret_cast<const float4*>(ApT + k0 * lda + 8);
            qa3 = *reinterpret_cast<const float4*>(ApT + k0 * lda + 12);
            qb0 = *reinterpret_cast<const float4*>(BpT + k0 * ldb);
            qb1 = *reinterpret_cast<const float4*>(BpT + k0 * ldb + 4);
            qb2 = *reinterpret_cast<const float4*>(BpT + k0 * ldb + 8);
            qb3 = *reinterpret_cast<const float4*>(BpT + k0 * ldb + 12);
        }
#pragma unroll
        for (int kb = 0; kb < 2; ++kb) {
            const int k1 = kb * 8 + tq, k2 = k1 + 4;
            unsigned af[4][4];
#pragma unroll
            for (int mt = 0; mt < 4; ++mt) {
                const int row = wm * 64 + mt * 16 + g;
                af[mt][0] = __float_as_uint(As[buf][k1][row]);
                af[mt][1] = __float_as_uint(As[buf][k1][row + 8]);
                af[mt][2] = __float_as_uint(As[buf][k2][row]);
                af[mt][3] = __float_as_uint(As[buf][k2][row + 8]);
            }
            unsigned bf[8][2];
#pragma unroll
            for (int nt = 0; nt < 8; ++nt) {
                const int col = wn * 64 + nt * 8 + g;
                bf[nt][0] = __float_as_uint(Bs[buf][k1][col]);
                bf[nt][1] = __float_as_uint(Bs[buf][k2][col]);
            }
#pragma unroll
            for (int mt = 0; mt < 4; ++mt)
#pragma unroll
                for (int nt = 0; nt < 8; ++nt) MMA_TF32(acc[mt][nt], af[mt], bf[nt]);
        }
        if (s + 1 < nSt) {
            const int nb = buf ^ 1;
            STS_TN(nb);
        }
        __syncthreads();
    }
#undef STS_TN

#pragma unroll
    for (int mt = 0; mt < 4; ++mt) {
        const int r1 = m0 + wm * 64 + mt * 16 + g;
        const int r2 = r1 + 8;
#pragma unroll
        for (int nt = 0; nt < 8; ++nt) {
            const int col = n0 + wn * 64 + nt * 8 + 2 * tq;
            Cb[(long)r1 * ldc + col]     = acc[mt][nt][0];
            Cb[(long)r1 * ldc + col + 1] = acc[mt][nt][1];
            Cb[(long)r2 * ldc + col]     = acc[mt][nt][2];
            Cb[(long)r2 * ldc + col + 1] = acc[mt][nt][3];
        }
    }
}

// ---------------------------------------------------------------------------
// LayerNorm over last dim (512). One warp per row, float4 vectorized.
// ---------------------------------------------------------------------------
__global__ void __launch_bounds__(256) ln_kernel(
    const float* __restrict__ in, float* __restrict__ out,
    const float* __restrict__ gamma, const float* __restrict__ beta, float eps) {
    const int warp = blockIdx.x * (blockDim.x >> 5) + (threadIdx.x >> 5);
    const int lane = threadIdx.x & 31;
    const float4* r = reinterpret_cast<const float4*>(in + (long)warp * 512);
    float4 v[4];
    float s = 0.f, s2 = 0.f;
#pragma unroll
    for (int i = 0; i < 4; ++i) {
        v[i] = r[lane + (i << 5)];
        s  += v[i].x + v[i].y + v[i].z + v[i].w;
        s2 += v[i].x * v[i].x + v[i].y * v[i].y + v[i].z * v[i].z + v[i].w * v[i].w;
    }
#pragma unroll
    for (int o = 16; o > 0; o >>= 1) {
        s  += __shfl_xor_sync(0xffffffffu, s, o);
        s2 += __shfl_xor_sync(0xffffffffu, s2, o);
    }
    const float mu = s * (1.f / 512.f);
    const float rstd = rsqrtf(s2 * (1.f / 512.f) - mu * mu + eps);
    float4* w = reinterpret_cast<float4*>(out + (long)warp * 512);
#pragma unroll
    for (int i = 0; i < 4; ++i) {
        const float4 g4 = reinterpret_cast<const float4*>(gamma)[lane + (i << 5)];
        const float4 b4 = reinterpret_cast<const float4*>(beta)[lane + (i << 5)];
        float4 o4;
        o4.x = (v[i].x - mu) * rstd * g4.x + b4.x;
        o4.y = (v[i].y - mu) * rstd * g4.y + b4.y;
        o4.z = (v[i].z - mu) * rstd * g4.z + b4.z;
        o4.w = (v[i].w - mu) * rstd * g4.w + b4.w;
        w[lane + (i << 5)] = o4;
    }
}

// ---------------------------------------------------------------------------
// InstanceNorm stats: per (b,h), mean/rstd over 512x512.
// ---------------------------------------------------------------------------
__global__ void __launch_bounds__(256) inorm_stats(const float* __restrict__ sc,
                                                   float* __restrict__ stats) {
    __shared__ float sh[256], sh2[256];
    const int z = blockIdx.x;
    const float4* p = reinterpret_cast<const float4*>(sc + (long)z * 262144);
    float s = 0.f, s2 = 0.f;
    for (int i = threadIdx.x; i < 65536; i += 256) {
        const float4 v = p[i];
        s  += v.x + v.y + v.z + v.w;
        s2 += v.x * v.x + v.y * v.y + v.z * v.z + v.w * v.w;
    }
    sh[threadIdx.x] = s; sh2[threadIdx.x] = s2;
    __syncthreads();
    for (int o = 128; o > 0; o >>= 1) {
        if (threadIdx.x < o) { sh[threadIdx.x] += sh[threadIdx.x + o]; sh2[threadIdx.x] += sh2[threadIdx.x + o]; }
        __syncthreads();
    }
    if (threadIdx.x == 0) {
        const float mu = sh[0] * (1.f / 262144.f);
        const float var = sh2[0] * (1.f / 262144.f) - mu * mu;
        stats[z * 2 + 0] = mu;
        stats[z * 2 + 1] = rsqrtf(var + 1e-5f);
    }
}

// ---------------------------------------------------------------------------
// Fused instance-norm-apply + softmax over rows of 512, in place. One warp/row.
// ---------------------------------------------------------------------------
__global__ void __launch_bounds__(256) softmax_rows(float* __restrict__ sc,
                                                    const float* __restrict__ stats) {
    const int warp = blockIdx.x * (blockDim.x >> 5) + (threadIdx.x >> 5);
    const int lane = threadIdx.x & 31;
    const int z = warp >> 9;
    const float mu = stats[z * 2 + 0];
    const float rstd = stats[z * 2 + 1];
    float4* row = reinterpret_cast<float4*>(sc + (long)warp * 512);
    float4 v[4];
    float mx = -1e30f;
#pragma unroll
    for (int i = 0; i < 4; ++i) {
        v[i] = row[lane + (i << 5)];
        v[i].x = (v[i].x - mu) * rstd; v[i].y = (v[i].y - mu) * rstd;
        v[i].z = (v[i].z - mu) * rstd; v[i].w = (v[i].w - mu) * rstd;
        mx = fmaxf(mx, fmaxf(fmaxf(v[i].x, v[i].y), fmaxf(v[i].z, v[i].w)));
    }
#pragma unroll
    for (int o = 16; o > 0; o >>= 1) mx = fmaxf(mx, __shfl_xor_sync(0xffffffffu, mx, o));
    float s = 0.f;
#pragma unroll
    for (int i = 0; i < 4; ++i) {
        v[i].x = __expf(v[i].x - mx); v[i].y = __expf(v[i].y - mx);
        v[i].z = __expf(v[i].z - mx); v[i].w = __expf(v[i].w - mx);
        s += v[i].x + v[i].y + v[i].z + v[i].w;
    }
#pragma unroll
    for (int o = 16; o > 0; o >>= 1) s += __shfl_xor_sync(0xffffffffu, s, o);
    const float inv = 1.f / s;
#pragma unroll
    for (int i = 0; i < 4; ++i) {
        v[i].x *= inv; v[i].y *= inv; v[i].z *= inv; v[i].w *= inv;
        row[lane + (i << 5)] = v[i];
    }
}

// ---------------------------------------------------------------------------
// Weight pre-processing (fp32 -> half, transposed/permuted)
// ---------------------------------------------------------------------------
__global__ void __launch_bounds__(256) transpose_rc_h(const float* __restrict__ in,
                                                      __half* __restrict__ out,
                                                      int rows, int cols) {
    // out[c*rows + r] = (half)in[r*cols + c]
    __shared__ float t[32][33];
    const int c0 = blockIdx.x << 5, r0 = blockIdx.y << 5;
    const int tx = threadIdx.x, ty = threadIdx.y;  // 32 x 8
#pragma unroll
    for (int j = 0; j < 32; j += 8) t[ty + j][tx] = in[(long)(r0 + ty + j) * cols + c0 + tx];
    __syncthreads();
#pragma unroll
    for (int j = 0; j < 32; j += 8)
        out[(long)(c0 + ty + j) * rows + r0 + tx] = __float2half_rn(t[tx][ty + j]);
}

__global__ void __launch_bounds__(256) permute_wo_h(const float* __restrict__ wo,
                                                    __half* __restrict__ woT) {
    // woT[o*4096 + h*512 + c] = (half)wo[(c*8+h)*512 + o]
    const long idx = (long)blockIdx.x * 256 + threadIdx.x;  // over 512*4096
    const int o = (int)(idx & 511);
    const int ch = (int)(idx >> 9);
    const int h = ch & 7;
    const int c = ch >> 3;
    woT[(long)o * 4096 + h * 512 + c] = __float2half_rn(wo[idx]);
}

// ---------------------------------------------------------------------------
// Host launcher
// ---------------------------------------------------------------------------
extern "C" void kernel_launch(void* const* d_in, const int* in_sizes, int n_in,
                              void* d_out, int out_size) {
    const float* x      = (const float*)d_in[0];
    const float* proj_w = (const float*)d_in[1];
    const float* proj_b = (const float*)d_in[2];
    const float* ln1_g  = (const float*)d_in[3];
    const float* ln1_b  = (const float*)d_in[4];
    const float* wq     = (const float*)d_in[5];
    const float* wk     = (const float*)d_in[6];
    const float* wv     = (const float*)d_in[7];
    const float* wo     = (const float*)d_in[8];
    const float* ln2_g  = (const float*)d_in[9];
    const float* ln2_b  = (const float*)d_in[10];
    const float* mo_w   = (const float*)d_in[11];
    const float* mo_b   = (const float*)d_in[12];
    float* out = (float*)d_out;

    float *emb, *xn, *q, *k, *v, *sc, *ob, *st;
    __half *wqTh, *wkTh, *wvTh, *woTh;
    cudaGetSymbolAddress((void**)&emb, g_emb);
    cudaGetSymbolAddress((void**)&xn,  g_xn);
    cudaGetSymbolAddress((void**)&q,   g_q);
    cudaGetSymbolAddress((void**)&k,   g_k);
    cudaGetSymbolAddress((void**)&v,   g_v);
    cudaGetSymbolAddress((void**)&sc,  g_sc);
    cudaGetSymbolAddress((void**)&ob,  g_ob);
    cudaGetSymbolAddress((void**)&st,  g_st);
    cudaGetSymbolAddress((void**)&wqTh, g_wqTh);
    cudaGetSymbolAddress((void**)&wkTh, g_wkTh);
    cudaGetSymbolAddress((void**)&wvTh, g_wvTh);
    cudaGetSymbolAddress((void**)&woTh, g_woTh);

    // Weight prep (fp32 -> half)
    transpose_rc_h<<<dim3(128, 16), dim3(32, 8)>>>(wq, wqTh, 512, 4096);
    transpose_rc_h<<<dim3(128, 16), dim3(32, 8)>>>(wk, wkTh, 512, 4096);
    transpose_rc_h<<<dim3(128, 16), dim3(32, 8)>>>(wv, wvTh, 512, 4096);
    permute_wo_h<<<8192, 256>>>(wo, woTh);

    // 1) Patch embed: emb[b,n,c] = sum_p proj_w[n,p]*x[b,c,p] + proj_b[n]
    //    M=256, N=512, K=256 (B = x, fp32)
    gemm_h_nt<1, 0><<<dim3(4, 2, 32), 128>>>(proj_w, 256, 0, 0,
                                             x, 256, 131072L, 0,
                                             emb, 512, 131072L, 0,
                                             256, 1, proj_b, 0);
    // 2) LN1
    ln_kernel<<<1024, 256>>>(emb, xn, ln1_g, ln1_b, 1e-6f);
    // 3) Q,K,V: M=256, N=4096, K=512 per batch (B = half weights)
    gemm_h_nt<0, 1><<<dim3(32, 2, 32), 128>>>(xn, 512, 131072L, 0, wqTh, 512, 0, 0,
                                              q, 4096, 1048576L, 0, 512, 1, nullptr, 0);
    gemm_h_nt<0, 1><<<dim3(32, 2, 32), 128>>>(xn, 512, 131072L, 0, wkTh, 512, 0, 0,
                                              k, 4096, 1048576L, 0, 512, 1, nullptr, 0);
    gemm_h_nt<0, 1><<<dim3(32, 2, 32), 128>>>(xn, 512, 131072L, 0, wvTh, 512, 0, 0,
                                              v, 4096, 1048576L, 0, 512, 1, nullptr, 0);
    // 4) Scores: per (b,h) M=512, N=512, K=256 (TN, tf32 legacy mma)
    gemm_tc_tn<<<dim3(4, 4, 256), 128>>>(q, 4096, 1048576L, 512, k, 4096, 1048576L, 512,
                                         sc, 512, 2097152L, 262144L, 256, 8);
    // 5) InstanceNorm stats + fused normalize+softmax (in place)
    inorm_stats<<<256, 256>>>(sc, st);
    softmax_rows<<<16384, 256>>>(sc, st);
    // 6) ctx2[b,n,h,i] = sum_j v[b,n,h,j]*attn[b,h,i,j]: M=256, N=512, K=512 per (b,h)
    //    (B = attn, fp32)
    gemm_h_nt<0, 0><<<dim3(4, 2, 256), 128>>>(v, 4096, 1048576L, 512, sc, 512, 2097152L, 262144L,
                                              q, 4096, 1048576L, 512, 512, 8, nullptr, 0);
    // 7) Out-proj + residual: M=256, N=512, K=4096 (B = half woT)
    gemm_h_nt<2, 1><<<dim3(4, 2, 32), 128>>>(q, 4096, 1048576L, 0, woTh, 4096, 0, 0,
                                             ob, 512, 131072L, 0, 4096, 1, emb, 131072L);
    // 8) LN2 (reuse g_xn)
    ln_kernel<<<1024, 256>>>(ob, xn, ln2_g, ln2_b, 1e-6f);
    // 9) 1x1 conv + bias + exact GELU, direct to d_out: M=512, N=256, K=512 (B = xn, fp32)
    gemm_h_nt<3, 0><<<dim3(2, 4, 32), 128>>>(mo_w, 512, 0, 0, xn, 512, 131072L, 0,
                                             out, 256, 131072L, 0, 512, 1, mo_b, 0);
}

// round 10
// speedup vs baseline: 6.3180x; 1.2430x over previous
#include <cuda_runtime.h>
#include <cuda_fp16.h>
#include <math.h>
#include <stdint.h>

// ---------------------------------------------------------------------------
// Problem constants (batch already halved: cat(x,x) duplicates, out[:b] keeps half)
//   B=32, C=512, N=256 (seq), H=8, P=256 (patch flat), HC=4096
// R9: identical to R8 submission (two prior broker failures were infra, not kernel).
// ---------------------------------------------------------------------------

__device__ float  g_emb[32 * 256 * 512];      //  (b, n, c) fp32 (residual)
__device__ float  g_ob [32 * 256 * 512];      //  out-proj + residual (fp32)
__device__ float  g_st [32 * 8 * 2];          //  instance-norm mean/rstd
__device__ __half g_xn [32 * 256 * 512];      //  LN outputs (half)
__device__ __half g_q  [32 * 256 * 4096];     //  (b, n, h*512+i); reused for ctx2
__device__ __half g_k  [32 * 256 * 4096];
__device__ __half g_v  [32 * 256 * 4096];
__device__ __half g_sc [32 * 8 * 512 * 512];  //  scores -> attn in place (half)
__device__ __half g_wqTh[4096 * 512];
__device__ __half g_wkTh[4096 * 512];
__device__ __half g_wvTh[4096 * 512];
__device__ __half g_woTh[512 * 4096];         //  woTh[o, h*512+c] = wo[c*8+h, o]

__device__ __forceinline__ float gelu_f(float x) {
    return 0.5f * x * (1.0f + erff(x * 0.70710678118654752f));
}

// fp16 MMA, fp32 accumulate: m16n8k16.
#define MMA_F16(c, a, b)                                                      \
    asm volatile(                                                             \
        "mma.sync.aligned.m16n8k16.row.col.f32.f16.f16.f32 "                  \
        "{%0,%1,%2,%3},{%4,%5,%6,%7},{%8,%9},{%0,%1,%2,%3};"                  \
        : "+f"(c[0]), "+f"(c[1]), "+f"(c[2]), "+f"(c[3])                      \
        : "r"(a[0]), "r"(a[1]), "r"(a[2]), "r"(a[3]), "r"(b[0]), "r"(b[1]))

#define MMA_TF32(c, a, b)                                                     \
    asm volatile(                                                             \
        "mma.sync.aligned.m16n8k8.row.col.f32.tf32.tf32.f32 "                 \
        "{%0,%1,%2,%3},{%4,%5,%6,%7},{%8,%9},{%0,%1,%2,%3};"                  \
        : "+f"(c[0]), "+f"(c[1]), "+f"(c[2]), "+f"(c[3])                      \
        : "r"(a[0]), "r"(a[1]), "r"(a[2]), "r"(a[3]), "r"(b[0]), "r"(b[1]))

__device__ __forceinline__ unsigned packh2(float a, float b) {
    const __half2 h = __floats2half2_rn(a, b);
    return *reinterpret_cast<const unsigned*>(&h);
}

// Unpack 8 halves (uint4) to 8 floats.
__device__ __forceinline__ void h8f(float* d, uint4 u) {
    const __half2* h = reinterpret_cast<const __half2*>(&u);
#pragma unroll
    for (int j = 0; j < 4; ++j) {
        const float2 f = __half22float2(h[j]);
        d[2 * j] = f.x; d[2 * j + 1] = f.y;
    }
}

// ---------------------------------------------------------------------------
// fp16 NT GEMM: C[m,n] = sum_k A[m,k]*B[n,k], K-contiguous operands.
// Tile 128x128, BK=16, 128 threads (4 warps 2x2, warp tile 64x64).
// AH/BH: operand is half (direct copy) vs fp32 (cvt in loader).
// OH: output half (plain store only) vs fp32 (EPI epilogues).
// EPI: 0 none | 1 +bias[m] | 2 +res[m*ldc+n] | 3 +bias[m] then exact GELU
// ---------------------------------------------------------------------------
template <int EPI, int AH, int BH, int OH>
__global__ void __launch_bounds__(128, 2) gemm_h_nt(
    const void* __restrict__ Av, int lda, long sAb, long sAh,
    const void* __restrict__ Bv, int ldb, long sBb, long sBh,
    void* __restrict__ Cv, int ldc, long sCb, long sCh,
    int K, int Hdiv, const float* __restrict__ ep, long sEpb) {
    __shared__ __align__(16) __half As[2][128][24];
    __shared__ __align__(16) __half Bs[2][128][24];
    const int z = blockIdx.z;
    const int b = z / Hdiv, h = z - b * Hdiv;
    const float*  Af = AH ? nullptr : ((const float*)Av + (long)b * sAb + (long)h * sAh);
    const __half* Ah = AH ? ((const __half*)Av + (long)b * sAb + (long)h * sAh) : nullptr;
    const float*  Bf = BH ? nullptr : ((const float*)Bv + (long)b * sBb + (long)h * sBh);
    const __half* Bh = BH ? ((const __half*)Bv + (long)b * sBb + (long)h * sBh) : nullptr;
    float*  Cf = OH ? nullptr : ((float*)Cv + (long)b * sCb + (long)h * sCh);
    __half* Ch = OH ? ((__half*)Cv + (long)b * sCb + (long)h * sCh) : nullptr;
    const float* epp = ep ? (ep + (long)b * sEpb) : ep;

    const int m0 = blockIdx.y << 7;
    const int n0 = blockIdx.x << 7;
    const int tid = threadIdx.x;
    const int warp = tid >> 5, lane = tid & 31;
    const int wm = warp & 1, wn = warp >> 1;   // 2m x 2n
    const int g = lane >> 2, tq = lane & 3;

    // Loader: rg = base row (0..31, +32p), cp4 = k offset (4 elements).
    const int rg = tid >> 2;
    const int cp4 = (tid & 3) << 2;

    float4 paf[4], pbf[4];
    uint2 pah[4], pbh[4];

#define LDG_STAGE(k0)                                                          \
    {                                                                          \
        _Pragma("unroll") for (int p = 0; p < 4; ++p) {                        \
            const int row = rg + p * 32;                                       \
            if (AH)                                                            \
                pah[p] = *reinterpret_cast<const uint2*>(                      \
                    Ah + (long)(m0 + row) * lda + (k0) + cp4);                 \
            else                                                               \
                paf[p] = *reinterpret_cast<const float4*>(                     \
                    Af + (long)(m0 + row) * lda + (k0) + cp4);                 \
            if (BH)                                                            \
                pbh[p] = *reinterpret_cast<const uint2*>(                      \
                    Bh + (long)(n0 + row) * ldb + (k0) + cp4);                 \
            else                                                               \
                pbf[p] = *reinterpret_cast<const float4*>(                     \
                    Bf + (long)(n0 + row) * ldb + (k0) + cp4);                 \
        }                                                                      \
    }
#define STS_STAGE(s)                                                           \
    {                                                                          \
        _Pragma("unroll") for (int p = 0; p < 4; ++p) {                        \
            const int row = rg + p * 32;                                       \
            uint2 ua;                                                          \
            if (AH) ua = pah[p];                                               \
            else { ua.x = packh2(paf[p].x, paf[p].y); ua.y = packh2(paf[p].z, paf[p].w); } \
            *reinterpret_cast<uint2*>(&As[s][row][cp4]) = ua;                  \
            uint2 ub;                                                          \
            if (BH) ub = pbh[p];                                               \
            else { ub.x = packh2(pbf[p].x, pbf[p].y); ub.y = packh2(pbf[p].z, pbf[p].w); } \
            *reinterpret_cast<uint2*>(&Bs[s][row][cp4]) = ub;                  \
        }                                                                      \
    }

    LDG_STAGE(0);
    STS_STAGE(0);
    __syncthreads();

    float acc[4][8][4] = {};
    const int nSt = K >> 4;
    for (int s = 0; s < nSt; ++s) {
        const int buf = s & 1;
        if (s + 1 < nSt) LDG_STAGE((s + 1) << 4);
        {
            unsigned af[4][4];
#pragma unroll
            for (int mt = 0; mt < 4; ++mt) {
                const int row = wm * 64 + mt * 16 + g;
                af[mt][0] = *reinterpret_cast<const unsigned*>(&As[buf][row][2 * tq]);
                af[mt][1] = *reinterpret_cast<const unsigned*>(&As[buf][row + 8][2 * tq]);
                af[mt][2] = *reinterpret_cast<const unsigned*>(&As[buf][row][2 * tq + 8]);
                af[mt][3] = *reinterpret_cast<const unsigned*>(&As[buf][row + 8][2 * tq + 8]);
            }
            unsigned bf[8][2];
#pragma unroll
            for (int nt = 0; nt < 8; ++nt) {
                const int col = wn * 64 + nt * 8 + g;
                bf[nt][0] = *reinterpret_cast<const unsigned*>(&Bs[buf][col][2 * tq]);
                bf[nt][1] = *reinterpret_cast<const unsigned*>(&Bs[buf][col][2 * tq + 8]);
            }
#pragma unroll
            for (int mt = 0; mt < 4; ++mt)
#pragma unroll
                for (int nt = 0; nt < 8; ++nt) MMA_F16(acc[mt][nt], af[mt], bf[nt]);
        }
        if (s + 1 < nSt) STS_STAGE(buf ^ 1);
        __syncthreads();
    }
#undef LDG_STAGE
#undef STS_STAGE

    // Epilogue
#pragma unroll
    for (int mt = 0; mt < 4; ++mt) {
        const int r1 = m0 + wm * 64 + mt * 16 + g;
        const int r2 = r1 + 8;
        float b1 = 0.f, b2 = 0.f;
        if (EPI == 1 || EPI == 3) { b1 = epp[r1]; b2 = epp[r2]; }
#pragma unroll
        for (int nt = 0; nt < 8; ++nt) {
            const int col = n0 + wn * 64 + nt * 8 + 2 * tq;
            float c0 = acc[mt][nt][0], c1 = acc[mt][nt][1];
            float c2 = acc[mt][nt][2], c3 = acc[mt][nt][3];
            if (OH) {
                *reinterpret_cast<__half2*>(Ch + (long)r1 * ldc + col) = __floats2half2_rn(c0, c1);
                *reinterpret_cast<__half2*>(Ch + (long)r2 * ldc + col) = __floats2half2_rn(c2, c3);
            } else {
                if (EPI == 1 || EPI == 3) { c0 += b1; c1 += b1; c2 += b2; c3 += b2; }
                if (EPI == 2) {
                    c0 += epp[(long)r1 * ldc + col];
                    c1 += epp[(long)r1 * ldc + col + 1];
                    c2 += epp[(long)r2 * ldc + col];
                    c3 += epp[(long)r2 * ldc + col + 1];
                }
                if (EPI == 3) {
                    c0 = gelu_f(c0); c1 = gelu_f(c1); c2 = gelu_f(c2); c3 = gelu_f(c3);
                }
                Cf[(long)r1 * ldc + col] = c0;
                Cf[(long)r1 * ldc + col + 1] = c1;
                Cf[(long)r2 * ldc + col] = c2;
                Cf[(long)r2 * ldc + col + 1] = c3;
            }
        }
    }
}

// ---------------------------------------------------------------------------
// TN GEMM (tf32 mma), half inputs/outputs: C[m,n] = sum_k A[k*lda+m]*B[k*ldb+n].
// Tile 128x128, BK=16, 128 threads (4 warps 2x2, warp tile 64x64). (scores)
// half->float is exact in tf32 (both 10-bit mantissa), so no cvt.rna needed.
// ---------------------------------------------------------------------------
__global__ void __launch_bounds__(128, 2) gemm_tc_tn(
    const __half* __restrict__ A, int lda, long sAb, long sAh,
    const __half* __restrict__ B, int ldb, long sBb, long sBh,
    __half* __restrict__ C, int ldc, long sCb, long sCh,
    int K, int Hdiv) {
    __shared__ __align__(16) float As[2][16][132];
    __shared__ __align__(16) float Bs[2][16][132];
    const int z = blockIdx.z;
    const int b = z / Hdiv, h = z - b * Hdiv;
    const __half* Ab = A + (long)b * sAb + (long)h * sAh;
    const __half* Bb = B + (long)b * sBb + (long)h * sBh;
    __half* Cb = C + (long)b * sCb + (long)h * sCh;

    const int m0 = blockIdx.y << 7;
    const int n0 = blockIdx.x << 7;
    const int tid = threadIdx.x;
    const int warp = tid >> 5, lane = tid & 31;
    const int wm = warp & 1, wn = warp >> 1;
    const int g = lane >> 2, tq = lane & 3;

    const int kr = tid >> 3;         // 0..15 (k row)
    const int mc = (tid & 7) << 4;   // 0..112 (m offset, 16 halves)
    const __half* ApT = Ab + (long)kr * lda + m0 + mc;
    const __half* BpT = Bb + (long)kr * ldb + n0 + mc;

    uint4 qa0 = *reinterpret_cast<const uint4*>(ApT);
    uint4 qa1 = *reinterpret_cast<const uint4*>(ApT + 8);
    uint4 qb0 = *reinterpret_cast<const uint4*>(BpT);
    uint4 qb1 = *reinterpret_cast<const uint4*>(BpT + 8);

#define STS_TN(s)                                                              \
    {                                                                          \
        h8f(&As[s][kr][mc], qa0);                                              \
        h8f(&As[s][kr][mc + 8], qa1);                                          \
        h8f(&Bs[s][kr][mc], qb0);                                              \
        h8f(&Bs[s][kr][mc + 8], qb1);                                          \
    }

    STS_TN(0);
    __syncthreads();

    float acc[4][8][4] = {};
    const int nSt = K >> 4;
    for (int s = 0; s < nSt; ++s) {
        const int buf = s & 1;
        if (s + 1 < nSt) {
            const long k0 = (long)((s + 1) << 4);
            qa0 = *reinterpret_cast<const uint4*>(ApT + k0 * lda);
            qa1 = *reinterpret_cast<const uint4*>(ApT + k0 * lda + 8);
            qb0 = *reinterpret_cast<const uint4*>(BpT + k0 * ldb);
            qb1 = *reinterpret_cast<const uint4*>(BpT + k0 * ldb + 8);
        }
#pragma unroll
        for (int kb = 0; kb < 2; ++kb) {
            const int k1 = kb * 8 + tq, k2 = k1 + 4;
            unsigned af[4][4];
#pragma unroll
            for (int mt = 0; mt < 4; ++mt) {
                const int row = wm * 64 + mt * 16 + g;
                af[mt][0] = __float_as_uint(As[buf][k1][row]);
                af[mt][1] = __float_as_uint(As[buf][k1][row + 8]);
                af[mt][2] = __float_as_uint(As[buf][k2][row]);
                af[mt][3] = __float_as_uint(As[buf][k2][row + 8]);
            }
            unsigned bf[8][2];
#pragma unroll
            for (int nt = 0; nt < 8; ++nt) {
                const int col = wn * 64 + nt * 8 + g;
                bf[nt][0] = __float_as_uint(Bs[buf][k1][col]);
                bf[nt][1] = __float_as_uint(Bs[buf][k2][col]);
            }
#pragma unroll
            for (int mt = 0; mt < 4; ++mt)
#pragma unroll
                for (int nt = 0; nt < 8; ++nt) MMA_TF32(acc[mt][nt], af[mt], bf[nt]);
        }
        if (s + 1 < nSt) {
            const int nb = buf ^ 1;
            STS_TN(nb);
        }
        __syncthreads();
    }
#undef STS_TN

#pragma unroll
    for (int mt = 0; mt < 4; ++mt) {
        const int r1 = m0 + wm * 64 + mt * 16 + g;
        const int r2 = r1 + 8;
#pragma unroll
        for (int nt = 0; nt < 8; ++nt) {
            const int col = n0 + wn * 64 + nt * 8 + 2 * tq;
            *reinterpret_cast<__half2*>(Cb + (long)r1 * ldc + col) =
                __floats2half2_rn(acc[mt][nt][0], acc[mt][nt][1]);
            *reinterpret_cast<__half2*>(Cb + (long)r2 * ldc + col) =
                __floats2half2_rn(acc[mt][nt][2], acc[mt][nt][3]);
        }
    }
}

// ---------------------------------------------------------------------------
// LayerNorm over last dim (512). One warp per row. fp32 in, half out.
// ---------------------------------------------------------------------------
__global__ void __launch_bounds__(256) ln_kernel(
    const float* __restrict__ in, __half* __restrict__ out,
    const float* __restrict__ gamma, const float* __restrict__ beta, float eps) {
    const int warp = blockIdx.x * (blockDim.x >> 5) + (threadIdx.x >> 5);
    const int lane = threadIdx.x & 31;
    const float4* r = reinterpret_cast<const float4*>(in + (long)warp * 512);
    float4 v[4];
    float s = 0.f, s2 = 0.f;
#pragma unroll
    for (int i = 0; i < 4; ++i) {
        v[i] = r[lane + (i << 5)];
        s  += v[i].x + v[i].y + v[i].z + v[i].w;
        s2 += v[i].x * v[i].x + v[i].y * v[i].y + v[i].z * v[i].z + v[i].w * v[i].w;
    }
#pragma unroll
    for (int o = 16; o > 0; o >>= 1) {
        s  += __shfl_xor_sync(0xffffffffu, s, o);
        s2 += __shfl_xor_sync(0xffffffffu, s2, o);
    }
    const float mu = s * (1.f / 512.f);
    const float rstd = rsqrtf(s2 * (1.f / 512.f) - mu * mu + eps);
    uint2* w = reinterpret_cast<uint2*>(out + (long)warp * 512);
#pragma unroll
    for (int i = 0; i < 4; ++i) {
        const float4 g4 = reinterpret_cast<const float4*>(gamma)[lane + (i << 5)];
        const float4 b4 = reinterpret_cast<const float4*>(beta)[lane + (i << 5)];
        uint2 o2;
        o2.x = packh2((v[i].x - mu) * rstd * g4.x + b4.x,
                      (v[i].y - mu) * rstd * g4.y + b4.y);
        o2.y = packh2((v[i].z - mu) * rstd * g4.z + b4.z,
                      (v[i].w - mu) * rstd * g4.w + b4.w);
        w[lane + (i << 5)] = o2;
    }
}

// ---------------------------------------------------------------------------
// InstanceNorm stats: per (b,h), mean/rstd over 512x512 (half input).
// ---------------------------------------------------------------------------
__global__ void __launch_bounds__(256) inorm_stats(const __half* __restrict__ sc,
                                                   float* __restrict__ stats) {
    __shared__ float sh[256], sh2[256];
    const int z = blockIdx.x;
    const uint4* p = reinterpret_cast<const uint4*>(sc + (long)z * 262144);
    float s = 0.f, s2 = 0.f;
    for (int i = threadIdx.x; i < 32768; i += 256) {  // 8 halves per uint4
        const uint4 u = p[i];
        float f[8];
        h8f(f, u);
#pragma unroll
        for (int j = 0; j < 8; ++j) { s += f[j]; s2 += f[j] * f[j]; }
    }
    sh[threadIdx.x] = s; sh2[threadIdx.x] = s2;
    __syncthreads();
    for (int o = 128; o > 0; o >>= 1) {
        if (threadIdx.x < o) { sh[threadIdx.x] += sh[threadIdx.x + o]; sh2[threadIdx.x] += sh2[threadIdx.x + o]; }
        __syncthreads();
    }
    if (threadIdx.x == 0) {
        const float mu = sh[0] * (1.f / 262144.f);
        const float var = sh2[0] * (1.f / 262144.f) - mu * mu;
        stats[z * 2 + 0] = mu;
        stats[z * 2 + 1] = rsqrtf(var + 1e-5f);
    }
}

// ---------------------------------------------------------------------------
// Fused instance-norm-apply + softmax over rows of 512, in place (half).
// One warp per row; each lane owns 16 halves (2 x uint4).
// ---------------------------------------------------------------------------
__global__ void __launch_bounds__(256) softmax_rows(__half* __restrict__ sc,
                                                    const float* __restrict__ stats) {
    const int warp = blockIdx.x * (blockDim.x >> 5) + (threadIdx.x >> 5);
    const int lane = threadIdx.x & 31;
    const int z = warp >> 9;
    const float mu = stats[z * 2 + 0];
    const float rstd = stats[z * 2 + 1];
    uint4* row = reinterpret_cast<uint4*>(sc + (long)warp * 512);
    const uint4 u0 = row[lane], u1 = row[lane + 32];
    float f[16];
    h8f(f, u0);
    h8f(f + 8, u1);
    float mx = -1e30f;
#pragma unroll
    for (int j = 0; j < 16; ++j) {
        f[j] = (f[j] - mu) * rstd;
        mx = fmaxf(mx, f[j]);
    }
#pragma unroll
    for (int o = 16; o > 0; o >>= 1) mx = fmaxf(mx, __shfl_xor_sync(0xffffffffu, mx, o));
    float s = 0.f;
#pragma unroll
    for (int j = 0; j < 16; ++j) { f[j] = __expf(f[j] - mx); s += f[j]; }
#pragma unroll
    for (int o = 16; o > 0; o >>= 1) s += __shfl_xor_sync(0xffffffffu, s, o);
    const float inv = 1.f / s;
    uint4 o0, o1;
    o0.x = packh2(f[0] * inv, f[1] * inv);   o0.y = packh2(f[2] * inv, f[3] * inv);
    o0.z = packh2(f[4] * inv, f[5] * inv);   o0.w = packh2(f[6] * inv, f[7] * inv);
    o1.x = packh2(f[8] * inv, f[9] * inv);   o1.y = packh2(f[10] * inv, f[11] * inv);
    o1.z = packh2(f[12] * inv, f[13] * inv); o1.w = packh2(f[14] * inv, f[15] * inv);
    row[lane] = o0;
    row[lane + 32] = o1;
}

// ---------------------------------------------------------------------------
// Weight pre-processing (fp32 -> half, transposed/permuted)
// ---------------------------------------------------------------------------
__global__ void __launch_bounds__(256) transpose_rc_h(const float* __restrict__ in,
                                                      __half* __restrict__ out,
                                                      int rows, int cols) {
    // out[c*rows + r] = (half)in[r*cols + c]
    __shared__ float t[32][33];
    const int c0 = blockIdx.x << 5, r0 = blockIdx.y << 5;
    const int tx = threadIdx.x, ty = threadIdx.y;  // 32 x 8
#pragma unroll
    for (int j = 0; j < 32; j += 8) t[ty + j][tx] = in[(long)(r0 + ty + j) * cols + c0 + tx];
    __syncthreads();
#pragma unroll
    for (int j = 0; j < 32; j += 8)
        out[(long)(c0 + ty + j) * rows + r0 + tx] = __float2half_rn(t[tx][ty + j]);
}

__global__ void __launch_bounds__(256) permute_wo_h(const float* __restrict__ wo,
                                                    __half* __restrict__ woT) {
    // woT[o*4096 + h*512 + c] = (half)wo[(c*8+h)*512 + o]
    const long idx = (long)blockIdx.x * 256 + threadIdx.x;  // over 512*4096
    const int o = (int)(idx & 511);
    const int ch = (int)(idx >> 9);
    const int h = ch & 7;
    const int c = ch >> 3;
    woT[(long)o * 4096 + h * 512 + c] = __float2half_rn(wo[idx]);
}

// ---------------------------------------------------------------------------
// Host launcher
// ---------------------------------------------------------------------------
extern "C" void kernel_launch(void* const* d_in, const int* in_sizes, int n_in,
                              void* d_out, int out_size) {
    const float* x      = (const float*)d_in[0];
    const float* proj_w = (const float*)d_in[1];
    const float* proj_b = (const float*)d_in[2];
    const float* ln1_g  = (const float*)d_in[3];
    const float* ln1_b  = (const float*)d_in[4];
    const float* wq     = (const float*)d_in[5];
    const float* wk     = (const float*)d_in[6];
    const float* wv     = (const float*)d_in[7];
    const float* wo     = (const float*)d_in[8];
    const float* ln2_g  = (const float*)d_in[9];
    const float* ln2_b  = (const float*)d_in[10];
    const float* mo_w   = (const float*)d_in[11];
    const float* mo_b   = (const float*)d_in[12];
    float* out = (float*)d_out;

    float *emb, *ob, *st;
    __half *xn, *q, *k, *v, *sc, *wqTh, *wkTh, *wvTh, *woTh;
    cudaGetSymbolAddress((void**)&emb, g_emb);
    cudaGetSymbolAddress((void**)&ob,  g_ob);
    cudaGetSymbolAddress((void**)&st,  g_st);
    cudaGetSymbolAddress((void**)&xn,  g_xn);
    cudaGetSymbolAddress((void**)&q,   g_q);
    cudaGetSymbolAddress((void**)&k,   g_k);
    cudaGetSymbolAddress((void**)&v,   g_v);
    cudaGetSymbolAddress((void**)&sc,  g_sc);
    cudaGetSymbolAddress((void**)&wqTh, g_wqTh);
    cudaGetSymbolAddress((void**)&wkTh, g_wkTh);
    cudaGetSymbolAddress((void**)&wvTh, g_wvTh);
    cudaGetSymbolAddress((void**)&woTh, g_woTh);

    // Weight prep (fp32 -> half)
    transpose_rc_h<<<dim3(128, 16), dim3(32, 8)>>>(wq, wqTh, 512, 4096);
    transpose_rc_h<<<dim3(128, 16), dim3(32, 8)>>>(wk, wkTh, 512, 4096);
    transpose_rc_h<<<dim3(128, 16), dim3(32, 8)>>>(wv, wvTh, 512, 4096);
    permute_wo_h<<<8192, 256>>>(wo, woTh);

    // 1) Patch embed: emb[b,n,c] (fp32) = proj_w @ x + proj_b. M=256,N=512,K=256
    gemm_h_nt<1, 0, 0, 0><<<dim3(4, 2, 32), 128>>>(proj_w, 256, 0, 0,
                                                   x, 256, 131072L, 0,
                                                   emb, 512, 131072L, 0,
                                                   256, 1, proj_b, 0);
    // 2) LN1 -> xn (half)
    ln_kernel<<<1024, 256>>>(emb, xn, ln1_g, ln1_b, 1e-6f);
    // 3) Q,K,V (half out): M=256, N=4096, K=512 per batch
    gemm_h_nt<0, 1, 1, 1><<<dim3(32, 2, 32), 128>>>(xn, 512, 131072L, 0, wqTh, 512, 0, 0,
                                                    q, 4096, 1048576L, 0, 512, 1, nullptr, 0);
    gemm_h_nt<0, 1, 1, 1><<<dim3(32, 2, 32), 128>>>(xn, 512, 131072L, 0, wkTh, 512, 0, 0,
                                                    k, 4096, 1048576L, 0, 512, 1, nullptr, 0);
    gemm_h_nt<0, 1, 1, 1><<<dim3(32, 2, 32), 128>>>(xn, 512, 131072L, 0, wvTh, 512, 0, 0,
                                                    v, 4096, 1048576L, 0, 512, 1, nullptr, 0);
    // 4) Scores (half in/out): per (b,h) M=512, N=512, K=256 (TN, tf32)
    gemm_tc_tn<<<dim3(4, 4, 256), 128>>>(q, 4096, 1048576L, 512, k, 4096, 1048576L, 512,
                                         sc, 512, 2097152L, 262144L, 256, 8);
    // 5) InstanceNorm stats + fused normalize+softmax (in place, half)
    inorm_stats<<<256, 256>>>(sc, st);
    softmax_rows<<<16384, 256>>>(sc, st);
    // 6) ctx2 (half out over g_q): M=256, N=512, K=512 per (b,h)
    gemm_h_nt<0, 1, 1, 1><<<dim3(4, 2, 256), 128>>>(v, 4096, 1048576L, 512, sc, 512, 2097152L, 262144L,
                                                    q, 4096, 1048576L, 512, 512, 8, nullptr, 0);
    // 7) Out-proj + residual (fp32 out): M=256, N=512, K=4096
    gemm_h_nt<2, 1, 1, 0><<<dim3(4, 2, 32), 128>>>(q, 4096, 1048576L, 0, woTh, 4096, 0, 0,
                                                   ob, 512, 131072L, 0, 4096, 1, emb, 131072L);
    // 8) LN2 -> xn (half)
    ln_kernel<<<1024, 256>>>(ob, xn, ln2_g, ln2_b, 1e-6f);
    // 9) 1x1 conv + bias + exact GELU, direct to d_out (fp32): M=512, N=256, K=512
    gemm_h_nt<3, 0, 1, 0><<<dim3(2, 4, 32), 128>>>(mo_w, 512, 0, 0, xn, 512, 131072L, 0,
                                                   out, 256, 131072L, 0, 512, 1, mo_b, 0);
}

// round 12
// speedup vs baseline: 6.9423x; 1.0988x over previous
#include <cuda_runtime.h>
#include <cuda_fp16.h>
#include <math.h>
#include <stdint.h>

// ---------------------------------------------------------------------------
// Problem constants (batch already halved: cat(x,x) duplicates, out[:b] keeps half)
//   B=32, C=512, N=256 (seq), H=8, P=256 (patch flat), HC=4096
// R12: identical to R11 submission (broker failed twice before running it;
//      same infra pattern as R8/R9 which ultimately ran fine unchanged).
//      q,k produced transposed (b, h*512+i, n) by QKV epilogue (OT mode);
//      scores runs on the fp16 NT path; tf32 kernel removed.
// ---------------------------------------------------------------------------

__device__ float  g_emb[32 * 256 * 512];      //  (b, n, c) fp32 (residual)
__device__ float  g_ob [32 * 256 * 512];      //  out-proj + residual (fp32)
__device__ float  g_st [32 * 8 * 2];          //  instance-norm mean/rstd
__device__ __half g_xn [32 * 256 * 512];      //  LN outputs (half)
__device__ __half g_q  [32 * 256 * 4096];     //  qT (b, h*512+i, n); reused for ctx2 (b,n,hi)
__device__ __half g_k  [32 * 256 * 4096];     //  kT (b, h*512+i, n)
__device__ __half g_v  [32 * 256 * 4096];     //  v  (b, n, h*512+j)
__device__ __half g_sc [32 * 8 * 512 * 512];  //  scores -> attn in place (half)
__device__ __half g_wqTh[4096 * 512];
__device__ __half g_wkTh[4096 * 512];
__device__ __half g_wvTh[4096 * 512];
__device__ __half g_woTh[512 * 4096];         //  woTh[o, h*512+c] = wo[c*8+h, o]

__device__ __forceinline__ float gelu_f(float x) {
    return 0.5f * x * (1.0f + erff(x * 0.70710678118654752f));
}

// fp16 MMA, fp32 accumulate: m16n8k16.
#define MMA_F16(c, a, b)                                                      \
    asm volatile(                                                             \
        "mma.sync.aligned.m16n8k16.row.col.f32.f16.f16.f32 "                  \
        "{%0,%1,%2,%3},{%4,%5,%6,%7},{%8,%9},{%0,%1,%2,%3};"                  \
        : "+f"(c[0]), "+f"(c[1]), "+f"(c[2]), "+f"(c[3])                      \
        : "r"(a[0]), "r"(a[1]), "r"(a[2]), "r"(a[3]), "r"(b[0]), "r"(b[1]))

__device__ __forceinline__ unsigned packh2(float a, float b) {
    const __half2 h = __floats2half2_rn(a, b);
    return *reinterpret_cast<const unsigned*>(&h);
}

// Unpack 8 halves (uint4) to 8 floats.
__device__ __forceinline__ void h8f(float* d, uint4 u) {
    const __half2* h = reinterpret_cast<const __half2*>(&u);
#pragma unroll
    for (int j = 0; j < 4; ++j) {
        const float2 f = __half22float2(h[j]);
        d[2 * j] = f.x; d[2 * j + 1] = f.y;
    }
}

// ---------------------------------------------------------------------------
// fp16 NT GEMM: C[m,n] = sum_k A[m,k]*B[n,k], K-contiguous operands.
// Tile 128x128, BK=16, 128 threads (4 warps 2x2, warp tile 64x64).
// AH/BH: operand is half (direct copy) vs fp32 (cvt in loader).
// OH: output half (plain store) vs fp32 (EPI epilogues).
// OT: output TRANSPOSED half: C[n*ldc + m] (requires OH=1, EPI=0).
// EPI: 0 none | 1 +bias[m] | 2 +res[m*ldc+n] | 3 +bias[m] then exact GELU
// ---------------------------------------------------------------------------
template <int EPI, int AH, int BH, int OH, int OT>
__global__ void __launch_bounds__(128, 2) gemm_h_nt(
    const void* __restrict__ Av, int lda, long sAb, long sAh,
    const void* __restrict__ Bv, int ldb, long sBb, long sBh,
    void* __restrict__ Cv, int ldc, long sCb, long sCh,
    int K, int Hdiv, const float* __restrict__ ep, long sEpb) {
    __shared__ __align__(16) __half As[2][128][24];
    __shared__ __align__(16) __half Bs[2][128][24];
    const int z = blockIdx.z;
    const int b = z / Hdiv, h = z - b * Hdiv;
    const float*  Af = AH ? nullptr : ((const float*)Av + (long)b * sAb + (long)h * sAh);
    const __half* Ah = AH ? ((const __half*)Av + (long)b * sAb + (long)h * sAh) : nullptr;
    const float*  Bf = BH ? nullptr : ((const float*)Bv + (long)b * sBb + (long)h * sBh);
    const __half* Bh = BH ? ((const __half*)Bv + (long)b * sBb + (long)h * sBh) : nullptr;
    float*  Cf = OH ? nullptr : ((float*)Cv + (long)b * sCb + (long)h * sCh);
    __half* Ch = OH ? ((__half*)Cv + (long)b * sCb + (long)h * sCh) : nullptr;
    const float* epp = ep ? (ep + (long)b * sEpb) : ep;

    const int m0 = blockIdx.y << 7;
    const int n0 = blockIdx.x << 7;
    const int tid = threadIdx.x;
    const int warp = tid >> 5, lane = tid & 31;
    const int wm = warp & 1, wn = warp >> 1;   // 2m x 2n
    const int g = lane >> 2, tq = lane & 3;

    // Loader: rg = base row (0..31, +32p), cp4 = k offset (4 elements).
    const int rg = tid >> 2;
    const int cp4 = (tid & 3) << 2;

    float4 paf[4], pbf[4];
    uint2 pah[4], pbh[4];

#define LDG_STAGE(k0)                                                          \
    {                                                                          \
        _Pragma("unroll") for (int p = 0; p < 4; ++p) {                        \
            const int row = rg + p * 32;                                       \
            if (AH)                                                            \
                pah[p] = *reinterpret_cast<const uint2*>(                      \
                    Ah + (long)(m0 + row) * lda + (k0) + cp4);                 \
            else                                                               \
                paf[p] = *reinterpret_cast<const float4*>(                     \
                    Af + (long)(m0 + row) * lda + (k0) + cp4);                 \
            if (BH)                                                            \
                pbh[p] = *reinterpret_cast<const uint2*>(                      \
                    Bh + (long)(n0 + row) * ldb + (k0) + cp4);                 \
            else                                                               \
                pbf[p] = *reinterpret_cast<const float4*>(                     \
                    Bf + (long)(n0 + row) * ldb + (k0) + cp4);                 \
        }                                                                      \
    }
#define STS_STAGE(s)                                                           \
    {                                                                          \
        _Pragma("unroll") for (int p = 0; p < 4; ++p) {                        \
            const int row = rg + p * 32;                                       \
            uint2 ua;                                                          \
            if (AH) ua = pah[p];                                               \
            else { ua.x = packh2(paf[p].x, paf[p].y); ua.y = packh2(paf[p].z, paf[p].w); } \
            *reinterpret_cast<uint2*>(&As[s][row][cp4]) = ua;                  \
            uint2 ub;                                                          \
            if (BH) ub = pbh[p];                                               \
            else { ub.x = packh2(pbf[p].x, pbf[p].y); ub.y = packh2(pbf[p].z, pbf[p].w); } \
            *reinterpret_cast<uint2*>(&Bs[s][row][cp4]) = ub;                  \
        }                                                                      \
    }

    LDG_STAGE(0);
    STS_STAGE(0);
    __syncthreads();

    float acc[4][8][4] = {};
    const int nSt = K >> 4;
    for (int s = 0; s < nSt; ++s) {
        const int buf = s & 1;
        if (s + 1 < nSt) LDG_STAGE((s + 1) << 4);
        {
            unsigned af[4][4];
#pragma unroll
            for (int mt = 0; mt < 4; ++mt) {
                const int row = wm * 64 + mt * 16 + g;
                af[mt][0] = *reinterpret_cast<const unsigned*>(&As[buf][row][2 * tq]);
                af[mt][1] = *reinterpret_cast<const unsigned*>(&As[buf][row + 8][2 * tq]);
                af[mt][2] = *reinterpret_cast<const unsigned*>(&As[buf][row][2 * tq + 8]);
                af[mt][3] = *reinterpret_cast<const unsigned*>(&As[buf][row + 8][2 * tq + 8]);
            }
            unsigned bf[8][2];
#pragma unroll
            for (int nt = 0; nt < 8; ++nt) {
                const int col = wn * 64 + nt * 8 + g;
                bf[nt][0] = *reinterpret_cast<const unsigned*>(&Bs[buf][col][2 * tq]);
                bf[nt][1] = *reinterpret_cast<const unsigned*>(&Bs[buf][col][2 * tq + 8]);
            }
#pragma unroll
            for (int mt = 0; mt < 4; ++mt)
#pragma unroll
                for (int nt = 0; nt < 8; ++nt) MMA_F16(acc[mt][nt], af[mt], bf[nt]);
        }
        if (s + 1 < nSt) STS_STAGE(buf ^ 1);
        __syncthreads();
    }
#undef LDG_STAGE
#undef STS_STAGE

    // Epilogue
#pragma unroll
    for (int mt = 0; mt < 4; ++mt) {
        const int r1 = m0 + wm * 64 + mt * 16 + g;
        const int r2 = r1 + 8;
        float b1 = 0.f, b2 = 0.f;
        if (EPI == 1 || EPI == 3) { b1 = epp[r1]; b2 = epp[r2]; }
#pragma unroll
        for (int nt = 0; nt < 8; ++nt) {
            const int col = n0 + wn * 64 + nt * 8 + 2 * tq;
            float c0 = acc[mt][nt][0], c1 = acc[mt][nt][1];
            float c2 = acc[mt][nt][2], c3 = acc[mt][nt][3];
            if (OT) {
                // Transposed store: C[col][row].
                Ch[(long)col * ldc + r1]       = __float2half_rn(c0);
                Ch[(long)(col + 1) * ldc + r1] = __float2half_rn(c1);
                Ch[(long)col * ldc + r2]       = __float2half_rn(c2);
                Ch[(long)(col + 1) * ldc + r2] = __float2half_rn(c3);
            } else if (OH) {
                *reinterpret_cast<__half2*>(Ch + (long)r1 * ldc + col) = __floats2half2_rn(c0, c1);
                *reinterpret_cast<__half2*>(Ch + (long)r2 * ldc + col) = __floats2half2_rn(c2, c3);
            } else {
                if (EPI == 1 || EPI == 3) { c0 += b1; c1 += b1; c2 += b2; c3 += b2; }
                if (EPI == 2) {
                    c0 += epp[(long)r1 * ldc + col];
                    c1 += epp[(long)r1 * ldc + col + 1];
                    c2 += epp[(long)r2 * ldc + col];
                    c3 += epp[(long)r2 * ldc + col + 1];
                }
                if (EPI == 3) {
                    c0 = gelu_f(c0); c1 = gelu_f(c1); c2 = gelu_f(c2); c3 = gelu_f(c3);
                }
                Cf[(long)r1 * ldc + col] = c0;
                Cf[(long)r1 * ldc + col + 1] = c1;
                Cf[(long)r2 * ldc + col] = c2;
                Cf[(long)r2 * ldc + col + 1] = c3;
            }
        }
    }
}

// ---------------------------------------------------------------------------
// LayerNorm over last dim (512). One warp per row. fp32 in, half out.
// ---------------------------------------------------------------------------
__global__ void __launch_bounds__(256) ln_kernel(
    const float* __restrict__ in, __half* __restrict__ out,
    const float* __restrict__ gamma, const float* __restrict__ beta, float eps) {
    const int warp = blockIdx.x * (blockDim.x >> 5) + (threadIdx.x >> 5);
    const int lane = threadIdx.x & 31;
    const float4* r = reinterpret_cast<const float4*>(in + (long)warp * 512);
    float4 v[4];
    float s = 0.f, s2 = 0.f;
#pragma unroll
    for (int i = 0; i < 4; ++i) {
        v[i] = r[lane + (i << 5)];
        s  += v[i].x + v[i].y + v[i].z + v[i].w;
        s2 += v[i].x * v[i].x + v[i].y * v[i].y + v[i].z * v[i].z + v[i].w * v[i].w;
    }
#pragma unroll
    for (int o = 16; o > 0; o >>= 1) {
        s  += __shfl_xor_sync(0xffffffffu, s, o);
        s2 += __shfl_xor_sync(0xffffffffu, s2, o);
    }
    const float mu = s * (1.f / 512.f);
    const float rstd = rsqrtf(s2 * (1.f / 512.f) - mu * mu + eps);
    uint2* w = reinterpret_cast<uint2*>(out + (long)warp * 512);
#pragma unroll
    for (int i = 0; i < 4; ++i) {
        const float4 g4 = reinterpret_cast<const float4*>(gamma)[lane + (i << 5)];
        const float4 b4 = reinterpret_cast<const float4*>(beta)[lane + (i << 5)];
        uint2 o2;
        o2.x = packh2((v[i].x - mu) * rstd * g4.x + b4.x,
                      (v[i].y - mu) * rstd * g4.y + b4.y);
        o2.y = packh2((v[i].z - mu) * rstd * g4.z + b4.z,
                      (v[i].w - mu) * rstd * g4.w + b4.w);
        w[lane + (i << 5)] = o2;
    }
}

// ---------------------------------------------------------------------------
// InstanceNorm stats: per (b,h), mean/rstd over 512x512 (half input).
// ---------------------------------------------------------------------------
__global__ void __launch_bounds__(256) inorm_stats(const __half* __restrict__ sc,
                                                   float* __restrict__ stats) {
    __shared__ float sh[256], sh2[256];
    const int z = blockIdx.x;
    const uint4* p = reinterpret_cast<const uint4*>(sc + (long)z * 262144);
    float s = 0.f, s2 = 0.f;
    for (int i = threadIdx.x; i < 32768; i += 256) {  // 8 halves per uint4
        const uint4 u = p[i];
        float f[8];
        h8f(f, u);
#pragma unroll
        for (int j = 0; j < 8; ++j) { s += f[j]; s2 += f[j] * f[j]; }
    }
    sh[threadIdx.x] = s; sh2[threadIdx.x] = s2;
    __syncthreads();
    for (int o = 128; o > 0; o >>= 1) {
        if (threadIdx.x < o) { sh[threadIdx.x] += sh[threadIdx.x + o]; sh2[threadIdx.x] += sh2[threadIdx.x + o]; }
        __syncthreads();
    }
    if (threadIdx.x == 0) {
        const float mu = sh[0] * (1.f / 262144.f);
        const float var = sh2[0] * (1.f / 262144.f) - mu * mu;
        stats[z * 2 + 0] = mu;
        stats[z * 2 + 1] = rsqrtf(var + 1e-5f);
    }
}

// ---------------------------------------------------------------------------
// Fused instance-norm-apply + softmax over rows of 512, in place (half).
// One warp per row; each lane owns 16 halves (2 x uint4).
// ---------------------------------------------------------------------------
__global__ void __launch_bounds__(256) softmax_rows(__half* __restrict__ sc,
                                                    const float* __restrict__ stats) {
    const int warp = blockIdx.x * (blockDim.x >> 5) + (threadIdx.x >> 5);
    const int lane = threadIdx.x & 31;
    const int z = warp >> 9;
    const float mu = stats[z * 2 + 0];
    const float rstd = stats[z * 2 + 1];
    uint4* row = reinterpret_cast<uint4*>(sc + (long)warp * 512);
    const uint4 u0 = row[lane], u1 = row[lane + 32];
    float f[16];
    h8f(f, u0);
    h8f(f + 8, u1);
    float mx = -1e30f;
#pragma unroll
    for (int j = 0; j < 16; ++j) {
        f[j] = (f[j] - mu) * rstd;
        mx = fmaxf(mx, f[j]);
    }
#pragma unroll
    for (int o = 16; o > 0; o >>= 1) mx = fmaxf(mx, __shfl_xor_sync(0xffffffffu, mx, o));
    float s = 0.f;
#pragma unroll
    for (int j = 0; j < 16; ++j) { f[j] = __expf(f[j] - mx); s += f[j]; }
#pragma unroll
    for (int o = 16; o > 0; o >>= 1) s += __shfl_xor_sync(0xffffffffu, s, o);
    const float inv = 1.f / s;
    uint4 o0, o1;
    o0.x = packh2(f[0] * inv, f[1] * inv);   o0.y = packh2(f[2] * inv, f[3] * inv);
    o0.z = packh2(f[4] * inv, f[5] * inv);   o0.w = packh2(f[6] * inv, f[7] * inv);
    o1.x = packh2(f[8] * inv, f[9] * inv);   o1.y = packh2(f[10] * inv, f[11] * inv);
    o1.z = packh2(f[12] * inv, f[13] * inv); o1.w = packh2(f[14] * inv, f[15] * inv);
    row[lane] = o0;
    row[lane + 32] = o1;
}

// ---------------------------------------------------------------------------
// Weight pre-processing (fp32 -> half, transposed/permuted)
// ---------------------------------------------------------------------------
__global__ void __launch_bounds__(256) transpose_rc_h(const float* __restrict__ in,
                                                      __half* __restrict__ out,
                                                      int rows, int cols) {
    // out[c*rows + r] = (half)in[r*cols + c]
    __shared__ float t[32][33];
    const int c0 = blockIdx.x << 5, r0 = blockIdx.y << 5;
    const int tx = threadIdx.x, ty = threadIdx.y;  // 32 x 8
#pragma unroll
    for (int j = 0; j < 32; j += 8) t[ty + j][tx] = in[(long)(r0 + ty + j) * cols + c0 + tx];
    __syncthreads();
#pragma unroll
    for (int j = 0; j < 32; j += 8)
        out[(long)(c0 + ty + j) * rows + r0 + tx] = __float2half_rn(t[tx][ty + j]);
}

__global__ void __launch_bounds__(256) permute_wo_h(const float* __restrict__ wo,
                                                    __half* __restrict__ woT) {
    // woT[o*4096 + h*512 + c] = (half)wo[(c*8+h)*512 + o]
    const long idx = (long)blockIdx.x * 256 + threadIdx.x;  // over 512*4096
    const int o = (int)(idx & 511);
    const int ch = (int)(idx >> 9);
    const int h = ch & 7;
    const int c = ch >> 3;
    woT[(long)o * 4096 + h * 512 + c] = __float2half_rn(wo[idx]);
}

// ---------------------------------------------------------------------------
// Host launcher
// ---------------------------------------------------------------------------
extern "C" void kernel_launch(void* const* d_in, const int* in_sizes, int n_in,
                              void* d_out, int out_size) {
    const float* x      = (const float*)d_in[0];
    const float* proj_w = (const float*)d_in[1];
    const float* proj_b = (const float*)d_in[2];
    const float* ln1_g  = (const float*)d_in[3];
    const float* ln1_b  = (const float*)d_in[4];
    const float* wq     = (const float*)d_in[5];
    const float* wk     = (const float*)d_in[6];
    const float* wv     = (const float*)d_in[7];
    const float* wo     = (const float*)d_in[8];
    const float* ln2_g  = (const float*)d_in[9];
    const float* ln2_b  = (const float*)d_in[10];
    const float* mo_w   = (const float*)d_in[11];
    const float* mo_b   = (const float*)d_in[12];
    float* out = (float*)d_out;

    float *emb, *ob, *st;
    __half *xn, *q, *k, *v, *sc, *wqTh, *wkTh, *wvTh, *woTh;
    cudaGetSymbolAddress((void**)&emb, g_emb);
    cudaGetSymbolAddress((void**)&ob,  g_ob);
    cudaGetSymbolAddress((void**)&st,  g_st);
    cudaGetSymbolAddress((void**)&xn,  g_xn);
    cudaGetSymbolAddress((void**)&q,   g_q);
    cudaGetSymbolAddress((void**)&k,   g_k);
    cudaGetSymbolAddress((void**)&v,   g_v);
    cudaGetSymbolAddress((void**)&sc,  g_sc);
    cudaGetSymbolAddress((void**)&wqTh, g_wqTh);
    cudaGetSymbolAddress((void**)&wkTh, g_wkTh);
    cudaGetSymbolAddress((void**)&wvTh, g_wvTh);
    cudaGetSymbolAddress((void**)&woTh, g_woTh);

    // Weight prep (fp32 -> half)
    transpose_rc_h<<<dim3(128, 16), dim3(32, 8)>>>(wq, wqTh, 512, 4096);
    transpose_rc_h<<<dim3(128, 16), dim3(32, 8)>>>(wk, wkTh, 512, 4096);
    transpose_rc_h<<<dim3(128, 16), dim3(32, 8)>>>(wv, wvTh, 512, 4096);
    permute_wo_h<<<8192, 256>>>(wo, woTh);

    // 1) Patch embed: emb[b,n,c] (fp32) = proj_w @ x + proj_b. M=256,N=512,K=256
    gemm_h_nt<1, 0, 0, 0, 0><<<dim3(4, 2, 32), 128>>>(proj_w, 256, 0, 0,
                                                      x, 256, 131072L, 0,
                                                      emb, 512, 131072L, 0,
                                                      256, 1, proj_b, 0);
    // 2) LN1 -> xn (half)
    ln_kernel<<<1024, 256>>>(emb, xn, ln1_g, ln1_b, 1e-6f);
    // 3) Q,K (TRANSPOSED half out: qT[b][hi][n], ldc=256), V (normal half out).
    //    M=256 (n), N=4096 (hi), K=512 per batch.
    gemm_h_nt<0, 1, 1, 1, 1><<<dim3(32, 2, 32), 128>>>(xn, 512, 131072L, 0, wqTh, 512, 0, 0,
                                                       q, 256, 1048576L, 0, 512, 1, nullptr, 0);
    gemm_h_nt<0, 1, 1, 1, 1><<<dim3(32, 2, 32), 128>>>(xn, 512, 131072L, 0, wkTh, 512, 0, 0,
                                                       k, 256, 1048576L, 0, 512, 1, nullptr, 0);
    gemm_h_nt<0, 1, 1, 1, 0><<<dim3(32, 2, 32), 128>>>(xn, 512, 131072L, 0, wvTh, 512, 0, 0,
                                                       v, 4096, 1048576L, 0, 512, 1, nullptr, 0);
    // 4) Scores (fp16 NT): per (b,h) scores[i][j] = sum_n qT[i][n]*kT[j][n].
    //    M=512, N=512, K=256; per-(b,h) strides: b=1048576, h=512*256=131072.
    gemm_h_nt<0, 1, 1, 1, 0><<<dim3(4, 4, 256), 128>>>(q, 256, 1048576L, 131072L,
                                                       k, 256, 1048576L, 131072L,
                                                       sc, 512, 2097152L, 262144L,
                                                       256, 8, nullptr, 0);
    // 5) InstanceNorm stats + fused normalize+softmax (in place, half)
    inorm_stats<<<256, 256>>>(sc, st);
    softmax_rows<<<16384, 256>>>(sc, st);
    // 6) ctx2 (half out over g_q, layout (b,n,hi)): ctx[n][i] = sum_j v[n][hj]*attn[i][j].
    //    M=256, N=512, K=512 per (b,h).
    gemm_h_nt<0, 1, 1, 1, 0><<<dim3(4, 2, 256), 128>>>(v, 4096, 1048576L, 512,
                                                       sc, 512, 2097152L, 262144L,
                                                       q, 4096, 1048576L, 512, 512, 8, nullptr, 0);
    // 7) Out-proj + residual (fp32 out): M=256, N=512, K=4096
    gemm_h_nt<2, 1, 1, 0, 0><<<dim3(4, 2, 32), 128>>>(q, 4096, 1048576L, 0, woTh, 4096, 0, 0,
                                                      ob, 512, 131072L, 0, 4096, 1, emb, 131072L);
    // 8) LN2 -> xn (half)
    ln_kernel<<<1024, 256>>>(ob, xn, ln2_g, ln2_b, 1e-6f);
    // 9) 1x1 conv + bias + exact GELU, direct to d_out (fp32): M=512, N=256, K=512
    gemm_h_nt<3, 0, 1, 0, 0><<<dim3(2, 4, 32), 128>>>(mo_w, 512, 0, 0, xn, 512, 131072L, 0,
                                                      out, 256, 131072L, 0, 512, 1, mo_b, 0);
}

// round 13
// speedup vs baseline: 7.0103x; 1.0098x over previous
#include <cuda_runtime.h>
#include <cuda_fp16.h>
#include <math.h>
#include <stdint.h>

// ---------------------------------------------------------------------------
// Problem constants (batch already halved: cat(x,x) duplicates, out[:b] keeps half)
//   B=32, C=512, N=256 (seq), H=8, P=256 (patch flat), HC=4096
// R13: instance-norm sum/sumsq folded into scores-GEMM epilogue (SP mode,
//      deterministic per-CTA partials in g_part); inorm_stats kernel deleted;
//      softmax_rows reduces partials and computes mu/rstd inline.
// ---------------------------------------------------------------------------

__device__ float  g_emb[32 * 256 * 512];      //  (b, n, c) fp32 (residual)
__device__ float  g_ob [32 * 256 * 512];      //  out-proj + residual (fp32)
__device__ float  g_part[256 * 32];           //  per-(b,h): 16 CTA x {sum, sumsq}
__device__ __half g_xn [32 * 256 * 512];      //  LN outputs (half)
__device__ __half g_q  [32 * 256 * 4096];     //  qT (b, h*512+i, n); reused for ctx2 (b,n,hi)
__device__ __half g_k  [32 * 256 * 4096];     //  kT (b, h*512+i, n)
__device__ __half g_v  [32 * 256 * 4096];     //  v  (b, n, h*512+j)
__device__ __half g_sc [32 * 8 * 512 * 512];  //  scores -> attn in place (half)
__device__ __half g_wqTh[4096 * 512];
__device__ __half g_wkTh[4096 * 512];
__device__ __half g_wvTh[4096 * 512];
__device__ __half g_woTh[512 * 4096];         //  woTh[o, h*512+c] = wo[c*8+h, o]

__device__ __forceinline__ float gelu_f(float x) {
    return 0.5f * x * (1.0f + erff(x * 0.70710678118654752f));
}

// fp16 MMA, fp32 accumulate: m16n8k16.
#define MMA_F16(c, a, b)                                                      \
    asm volatile(                                                             \
        "mma.sync.aligned.m16n8k16.row.col.f32.f16.f16.f32 "                  \
        "{%0,%1,%2,%3},{%4,%5,%6,%7},{%8,%9},{%0,%1,%2,%3};"                  \
        : "+f"(c[0]), "+f"(c[1]), "+f"(c[2]), "+f"(c[3])                      \
        : "r"(a[0]), "r"(a[1]), "r"(a[2]), "r"(a[3]), "r"(b[0]), "r"(b[1]))

__device__ __forceinline__ unsigned packh2(float a, float b) {
    const __half2 h = __floats2half2_rn(a, b);
    return *reinterpret_cast<const unsigned*>(&h);
}

// Unpack 8 halves (uint4) to 8 floats.
__device__ __forceinline__ void h8f(float* d, uint4 u) {
    const __half2* h = reinterpret_cast<const __half2*>(&u);
#pragma unroll
    for (int j = 0; j < 4; ++j) {
        const float2 f = __half22float2(h[j]);
        d[2 * j] = f.x; d[2 * j + 1] = f.y;
    }
}

// ---------------------------------------------------------------------------
// fp16 NT GEMM: C[m,n] = sum_k A[m,k]*B[n,k], K-contiguous operands.
// Tile 128x128, BK=16, 128 threads (4 warps 2x2, warp tile 64x64).
// AH/BH: operand is half (direct copy) vs fp32 (cvt in loader).
// OH: output half (plain store) vs fp32 (EPI epilogues).
// OT: output TRANSPOSED half: C[n*ldc + m] (requires OH=1, EPI=0).
// SP: also block-reduce sum/sumsq of the fp32 tile into part[z*32 + tile*2].
// EPI: 0 none | 1 +bias[m] | 2 +res[m*ldc+n] | 3 +bias[m] then exact GELU
// ---------------------------------------------------------------------------
template <int EPI, int AH, int BH, int OH, int OT, int SP>
__global__ void __launch_bounds__(128, 2) gemm_h_nt(
    const void* __restrict__ Av, int lda, long sAb, long sAh,
    const void* __restrict__ Bv, int ldb, long sBb, long sBh,
    void* __restrict__ Cv, int ldc, long sCb, long sCh,
    int K, int Hdiv, const float* __restrict__ ep, long sEpb,
    float* __restrict__ part) {
    __shared__ __align__(16) __half As[2][128][24];
    __shared__ __align__(16) __half Bs[2][128][24];
    const int z = blockIdx.z;
    const int b = z / Hdiv, h = z - b * Hdiv;
    const float*  Af = AH ? nullptr : ((const float*)Av + (long)b * sAb + (long)h * sAh);
    const __half* Ah = AH ? ((const __half*)Av + (long)b * sAb + (long)h * sAh) : nullptr;
    const float*  Bf = BH ? nullptr : ((const float*)Bv + (long)b * sBb + (long)h * sBh);
    const __half* Bh = BH ? ((const __half*)Bv + (long)b * sBb + (long)h * sBh) : nullptr;
    float*  Cf = OH ? nullptr : ((float*)Cv + (long)b * sCb + (long)h * sCh);
    __half* Ch = OH ? ((__half*)Cv + (long)b * sCb + (long)h * sCh) : nullptr;
    const float* epp = ep ? (ep + (long)b * sEpb) : ep;

    const int m0 = blockIdx.y << 7;
    const int n0 = blockIdx.x << 7;
    const int tid = threadIdx.x;
    const int warp = tid >> 5, lane = tid & 31;
    const int wm = warp & 1, wn = warp >> 1;   // 2m x 2n
    const int g = lane >> 2, tq = lane & 3;

    // Loader: rg = base row (0..31, +32p), cp4 = k offset (4 elements).
    const int rg = tid >> 2;
    const int cp4 = (tid & 3) << 2;

    float4 paf[4], pbf[4];
    uint2 pah[4], pbh[4];

#define LDG_STAGE(k0)                                                          \
    {                                                                          \
        _Pragma("unroll") for (int p = 0; p < 4; ++p) {                        \
            const int row = rg + p * 32;                                       \
            if (AH)                                                            \
                pah[p] = *reinterpret_cast<const uint2*>(                      \
                    Ah + (long)(m0 + row) * lda + (k0) + cp4);                 \
            else                                                               \
                paf[p] = *reinterpret_cast<const float4*>(                     \
                    Af + (long)(m0 + row) * lda + (k0) + cp4);                 \
            if (BH)                                                            \
                pbh[p] = *reinterpret_cast<const uint2*>(                      \
                    Bh + (long)(n0 + row) * ldb + (k0) + cp4);                 \
            else                                                               \
                pbf[p] = *reinterpret_cast<const float4*>(                     \
                    Bf + (long)(n0 + row) * ldb + (k0) + cp4);                 \
        }                                                                      \
    }
#define STS_STAGE(s)                                                           \
    {                                                                          \
        _Pragma("unroll") for (int p = 0; p < 4; ++p) {                        \
            const int row = rg + p * 32;                                       \
            uint2 ua;                                                          \
            if (AH) ua = pah[p];                                               \
            else { ua.x = packh2(paf[p].x, paf[p].y); ua.y = packh2(paf[p].z, paf[p].w); } \
            *reinterpret_cast<uint2*>(&As[s][row][cp4]) = ua;                  \
            uint2 ub;                                                          \
            if (BH) ub = pbh[p];                                               \
            else { ub.x = packh2(pbf[p].x, pbf[p].y); ub.y = packh2(pbf[p].z, pbf[p].w); } \
            *reinterpret_cast<uint2*>(&Bs[s][row][cp4]) = ub;                  \
        }                                                                      \
    }

    LDG_STAGE(0);
    STS_STAGE(0);
    __syncthreads();

    float acc[4][8][4] = {};
    const int nSt = K >> 4;
    for (int s = 0; s < nSt; ++s) {
        const int buf = s & 1;
        if (s + 1 < nSt) LDG_STAGE((s + 1) << 4);
        {
            unsigned af[4][4];
#pragma unroll
            for (int mt = 0; mt < 4; ++mt) {
                const int row = wm * 64 + mt * 16 + g;
                af[mt][0] = *reinterpret_cast<const unsigned*>(&As[buf][row][2 * tq]);
                af[mt][1] = *reinterpret_cast<const unsigned*>(&As[buf][row + 8][2 * tq]);
                af[mt][2] = *reinterpret_cast<const unsigned*>(&As[buf][row][2 * tq + 8]);
                af[mt][3] = *reinterpret_cast<const unsigned*>(&As[buf][row + 8][2 * tq + 8]);
            }
            unsigned bf[8][2];
#pragma unroll
            for (int nt = 0; nt < 8; ++nt) {
                const int col = wn * 64 + nt * 8 + g;
                bf[nt][0] = *reinterpret_cast<const unsigned*>(&Bs[buf][col][2 * tq]);
                bf[nt][1] = *reinterpret_cast<const unsigned*>(&Bs[buf][col][2 * tq + 8]);
            }
#pragma unroll
            for (int mt = 0; mt < 4; ++mt)
#pragma unroll
                for (int nt = 0; nt < 8; ++nt) MMA_F16(acc[mt][nt], af[mt], bf[nt]);
        }
        if (s + 1 < nSt) STS_STAGE(buf ^ 1);
        __syncthreads();
    }
#undef LDG_STAGE
#undef STS_STAGE

    // Epilogue
#pragma unroll
    for (int mt = 0; mt < 4; ++mt) {
        const int r1 = m0 + wm * 64 + mt * 16 + g;
        const int r2 = r1 + 8;
        float b1 = 0.f, b2 = 0.f;
        if (EPI == 1 || EPI == 3) { b1 = epp[r1]; b2 = epp[r2]; }
#pragma unroll
        for (int nt = 0; nt < 8; ++nt) {
            const int col = n0 + wn * 64 + nt * 8 + 2 * tq;
            float c0 = acc[mt][nt][0], c1 = acc[mt][nt][1];
            float c2 = acc[mt][nt][2], c3 = acc[mt][nt][3];
            if (OT) {
                // Transposed store: C[col][row].
                Ch[(long)col * ldc + r1]       = __float2half_rn(c0);
                Ch[(long)(col + 1) * ldc + r1] = __float2half_rn(c1);
                Ch[(long)col * ldc + r2]       = __float2half_rn(c2);
                Ch[(long)(col + 1) * ldc + r2] = __float2half_rn(c3);
            } else if (OH) {
                *reinterpret_cast<__half2*>(Ch + (long)r1 * ldc + col) = __floats2half2_rn(c0, c1);
                *reinterpret_cast<__half2*>(Ch + (long)r2 * ldc + col) = __floats2half2_rn(c2, c3);
            } else {
                if (EPI == 1 || EPI == 3) { c0 += b1; c1 += b1; c2 += b2; c3 += b2; }
                if (EPI == 2) {
                    c0 += epp[(long)r1 * ldc + col];
                    c1 += epp[(long)r1 * ldc + col + 1];
                    c2 += epp[(long)r2 * ldc + col];
                    c3 += epp[(long)r2 * ldc + col + 1];
                }
                if (EPI == 3) {
                    c0 = gelu_f(c0); c1 = gelu_f(c1); c2 = gelu_f(c2); c3 = gelu_f(c3);
                }
                Cf[(long)r1 * ldc + col] = c0;
                Cf[(long)r1 * ldc + col + 1] = c1;
                Cf[(long)r2 * ldc + col] = c2;
                Cf[(long)r2 * ldc + col + 1] = c3;
            }
        }
    }

    if (SP) {
        // Deterministic per-CTA sum/sumsq of the fp32 tile -> part[z*32 + tile*2].
        float s = 0.f, s2 = 0.f;
#pragma unroll
        for (int mt = 0; mt < 4; ++mt)
#pragma unroll
            for (int nt = 0; nt < 8; ++nt)
#pragma unroll
                for (int i = 0; i < 4; ++i) {
                    const float v = acc[mt][nt][i];
                    s += v; s2 += v * v;
                }
        float* red = reinterpret_cast<float*>(As);  // reuse smem (post-sync safe)
        __syncthreads();
        red[tid] = s; red[128 + tid] = s2;
        __syncthreads();
        for (int o = 64; o > 0; o >>= 1) {
            if (tid < o) {
                red[tid] += red[tid + o];
                red[128 + tid] += red[128 + tid + o];
            }
            __syncthreads();
        }
        if (tid == 0) {
            const int t = blockIdx.y * gridDim.x + blockIdx.x;  // 0..15
            part[(long)z * 32 + t * 2 + 0] = red[0];
            part[(long)z * 32 + t * 2 + 1] = red[128];
        }
    }
}

// ---------------------------------------------------------------------------
// LayerNorm over last dim (512). One warp per row. fp32 in, half out.
// ---------------------------------------------------------------------------
__global__ void __launch_bounds__(256) ln_kernel(
    const float* __restrict__ in, __half* __restrict__ out,
    const float* __restrict__ gamma, const float* __restrict__ beta, float eps) {
    const int warp = blockIdx.x * (blockDim.x >> 5) + (threadIdx.x >> 5);
    const int lane = threadIdx.x & 31;
    const float4* r = reinterpret_cast<const float4*>(in + (long)warp * 512);
    float4 v[4];
    float s = 0.f, s2 = 0.f;
#pragma unroll
    for (int i = 0; i < 4; ++i) {
        v[i] = r[lane + (i << 5)];
        s  += v[i].x + v[i].y + v[i].z + v[i].w;
        s2 += v[i].x * v[i].x + v[i].y * v[i].y + v[i].z * v[i].z + v[i].w * v[i].w;
    }
#pragma unroll
    for (int o = 16; o > 0; o >>= 1) {
        s  += __shfl_xor_sync(0xffffffffu, s, o);
        s2 += __shfl_xor_sync(0xffffffffu, s2, o);
    }
    const float mu = s * (1.f / 512.f);
    const float rstd = rsqrtf(s2 * (1.f / 512.f) - mu * mu + eps);
    uint2* w = reinterpret_cast<uint2*>(out + (long)warp * 512);
#pragma unroll
    for (int i = 0; i < 4; ++i) {
        const float4 g4 = reinterpret_cast<const float4*>(gamma)[lane + (i << 5)];
        const float4 b4 = reinterpret_cast<const float4*>(beta)[lane + (i << 5)];
        uint2 o2;
        o2.x = packh2((v[i].x - mu) * rstd * g4.x + b4.x,
                      (v[i].y - mu) * rstd * g4.y + b4.y);
        o2.y = packh2((v[i].z - mu) * rstd * g4.z + b4.z,
                      (v[i].w - mu) * rstd * g4.w + b4.w);
        w[lane + (i << 5)] = o2;
    }
}

// ---------------------------------------------------------------------------
// Fused instance-norm + softmax over rows of 512, in place (half).
// mu/rstd derived from the 16 per-CTA partials written by the scores GEMM.
// One warp per row; each lane owns 16 halves (2 x uint4).
// ---------------------------------------------------------------------------
__global__ void __launch_bounds__(256) softmax_rows(__half* __restrict__ sc,
                                                    const float* __restrict__ part) {
    const int warp = blockIdx.x * (blockDim.x >> 5) + (threadIdx.x >> 5);
    const int lane = threadIdx.x & 31;
    const int z = warp >> 9;
    const float* pz = part + (long)z * 32;
    float s0 = 0.f, q0 = 0.f;
#pragma unroll
    for (int t = 0; t < 16; ++t) { s0 += pz[2 * t]; q0 += pz[2 * t + 1]; }
    const float mu = s0 * (1.f / 262144.f);
    const float var = q0 * (1.f / 262144.f) - mu * mu;
    const float rstd = rsqrtf(var + 1e-5f);

    uint4* row = reinterpret_cast<uint4*>(sc + (long)warp * 512);
    const uint4 u0 = row[lane], u1 = row[lane + 32];
    float f[16];
    h8f(f, u0);
    h8f(f + 8, u1);
    float mx = -1e30f;
#pragma unroll
    for (int j = 0; j < 16; ++j) {
        f[j] = (f[j] - mu) * rstd;
        mx = fmaxf(mx, f[j]);
    }
#pragma unroll
    for (int o = 16; o > 0; o >>= 1) mx = fmaxf(mx, __shfl_xor_sync(0xffffffffu, mx, o));
    float s = 0.f;
#pragma unroll
    for (int j = 0; j < 16; ++j) { f[j] = __expf(f[j] - mx); s += f[j]; }
#pragma unroll
    for (int o = 16; o > 0; o >>= 1) s += __shfl_xor_sync(0xffffffffu, s, o);
    const float inv = 1.f / s;
    uint4 o0, o1;
    o0.x = packh2(f[0] * inv, f[1] * inv);   o0.y = packh2(f[2] * inv, f[3] * inv);
    o0.z = packh2(f[4] * inv, f[5] * inv);   o0.w = packh2(f[6] * inv, f[7] * inv);
    o1.x = packh2(f[8] * inv, f[9] * inv);   o1.y = packh2(f[10] * inv, f[11] * inv);
    o1.z = packh2(f[12] * inv, f[13] * inv); o1.w = packh2(f[14] * inv, f[15] * inv);
    row[lane] = o0;
    row[lane + 32] = o1;
}

// ---------------------------------------------------------------------------
// Weight pre-processing (fp32 -> half, transposed/permuted)
// ---------------------------------------------------------------------------
__global__ void __launch_bounds__(256) transpose_rc_h(const float* __restrict__ in,
                                                      __half* __restrict__ out,
                                                      int rows, int cols) {
    // out[c*rows + r] = (half)in[r*cols + c]
    __shared__ float t[32][33];
    const int c0 = blockIdx.x << 5, r0 = blockIdx.y << 5;
    const int tx = threadIdx.x, ty = threadIdx.y;  // 32 x 8
#pragma unroll
    for (int j = 0; j < 32; j += 8) t[ty + j][tx] = in[(long)(r0 + ty + j) * cols + c0 + tx];
    __syncthreads();
#pragma unroll
    for (int j = 0; j < 32; j += 8)
        out[(long)(c0 + ty + j) * rows + r0 + tx] = __float2half_rn(t[tx][ty + j]);
}

__global__ void __launch_bounds__(256) permute_wo_h(const float* __restrict__ wo,
                                                    __half* __restrict__ woT) {
    // woT[o*4096 + h*512 + c] = (half)wo[(c*8+h)*512 + o]
    const long idx = (long)blockIdx.x * 256 + threadIdx.x;  // over 512*4096
    const int o = (int)(idx & 511);
    const int ch = (int)(idx >> 9);
    const int h = ch & 7;
    const int c = ch >> 3;
    woT[(long)o * 4096 + h * 512 + c] = __float2half_rn(wo[idx]);
}

// ---------------------------------------------------------------------------
// Host launcher
// ---------------------------------------------------------------------------
extern "C" void kernel_launch(void* const* d_in, const int* in_sizes, int n_in,
                              void* d_out, int out_size) {
    const float* x      = (const float*)d_in[0];
    const float* proj_w = (const float*)d_in[1];
    const float* proj_b = (const float*)d_in[2];
    const float* ln1_g  = (const float*)d_in[3];
    const float* ln1_b  = (const float*)d_in[4];
    const float* wq     = (const float*)d_in[5];
    const float* wk     = (const float*)d_in[6];
    const float* wv     = (const float*)d_in[7];
    const float* wo     = (const float*)d_in[8];
    const float* ln2_g  = (const float*)d_in[9];
    const float* ln2_b  = (const float*)d_in[10];
    const float* mo_w   = (const float*)d_in[11];
    const float* mo_b   = (const float*)d_in[12];
    float* out = (float*)d_out;

    float *emb, *ob, *part;
    __half *xn, *q, *k, *v, *sc, *wqTh, *wkTh, *wvTh, *woTh;
    cudaGetSymbolAddress((void**)&emb,  g_emb);
    cudaGetSymbolAddress((void**)&ob,   g_ob);
    cudaGetSymbolAddress((void**)&part, g_part);
    cudaGetSymbolAddress((void**)&xn,   g_xn);
    cudaGetSymbolAddress((void**)&q,    g_q);
    cudaGetSymbolAddress((void**)&k,    g_k);
    cudaGetSymbolAddress((void**)&v,    g_v);
    cudaGetSymbolAddress((void**)&sc,   g_sc);
    cudaGetSymbolAddress((void**)&wqTh, g_wqTh);
    cudaGetSymbolAddress((void**)&wkTh, g_wkTh);
    cudaGetSymbolAddress((void**)&wvTh, g_wvTh);
    cudaGetSymbolAddress((void**)&woTh, g_woTh);

    // Weight prep (fp32 -> half)
    transpose_rc_h<<<dim3(128, 16), dim3(32, 8)>>>(wq, wqTh, 512, 4096);
    transpose_rc_h<<<dim3(128, 16), dim3(32, 8)>>>(wk, wkTh, 512, 4096);
    transpose_rc_h<<<dim3(128, 16), dim3(32, 8)>>>(wv, wvTh, 512, 4096);
    permute_wo_h<<<8192, 256>>>(wo, woTh);

    // 1) Patch embed: emb[b,n,c] (fp32) = proj_w @ x + proj_b. M=256,N=512,K=256
    gemm_h_nt<1, 0, 0, 0, 0, 0><<<dim3(4, 2, 32), 128>>>(proj_w, 256, 0, 0,
                                                         x, 256, 131072L, 0,
                                                         emb, 512, 131072L, 0,
                                                         256, 1, proj_b, 0, nullptr);
    // 2) LN1 -> xn (half)
    ln_kernel<<<1024, 256>>>(emb, xn, ln1_g, ln1_b, 1e-6f);
    // 3) Q,K (TRANSPOSED half out: qT[b][hi][n], ldc=256), V (normal half out).
    //    M=256 (n), N=4096 (hi), K=512 per batch.
    gemm_h_nt<0, 1, 1, 1, 1, 0><<<dim3(32, 2, 32), 128>>>(xn, 512, 131072L, 0, wqTh, 512, 0, 0,
                                                          q, 256, 1048576L, 0, 512, 1, nullptr, 0, nullptr);
    gemm_h_nt<0, 1, 1, 1, 1, 0><<<dim3(32, 2, 32), 128>>>(xn, 512, 131072L, 0, wkTh, 512, 0, 0,
                                                          k, 256, 1048576L, 0, 512, 1, nullptr, 0, nullptr);
    gemm_h_nt<0, 1, 1, 1, 0, 0><<<dim3(32, 2, 32), 128>>>(xn, 512, 131072L, 0, wvTh, 512, 0, 0,
                                                          v, 4096, 1048576L, 0, 512, 1, nullptr, 0, nullptr);
    // 4) Scores (fp16 NT, + SP partial sums): per (b,h) scores[i][j] = sum_n qT[i][n]*kT[j][n].
    //    M=512, N=512, K=256; per-(b,h) strides: b=1048576, h=512*256=131072.
    gemm_h_nt<0, 1, 1, 1, 0, 1><<<dim3(4, 4, 256), 128>>>(q, 256, 1048576L, 131072L,
                                                          k, 256, 1048576L, 131072L,
                                                          sc, 512, 2097152L, 262144L,
                                                          256, 8, nullptr, 0, part);
    // 5) Fused instance-norm (stats from partials) + softmax (in place, half)
    softmax_rows<<<16384, 256>>>(sc, part);
    // 6) ctx2 (half out over g_q, layout (b,n,hi)): ctx[n][i] = sum_j v[n][hj]*attn[i][j].
    //    M=256, N=512, K=512 per (b,h).
    gemm_h_nt<0, 1, 1, 1, 0, 0><<<dim3(4, 2, 256), 128>>>(v, 4096, 1048576L, 512,
                                                          sc, 512, 2097152L, 262144L,
                                                          q, 4096, 1048576L, 512, 512, 8, nullptr, 0, nullptr);
    // 7) Out-proj + residual (fp32 out): M=256, N=512, K=4096
    gemm_h_nt<2, 1, 1, 0, 0, 0><<<dim3(4, 2, 32), 128>>>(q, 4096, 1048576L, 0, woTh, 4096, 0, 0,
                                                         ob, 512, 131072L, 0, 4096, 1, emb, 131072L, nullptr);
    // 8) LN2 -> xn (half)
    ln_kernel<<<1024, 256>>>(ob, xn, ln2_g, ln2_b, 1e-6f);
    // 9) 1x1 conv + bias + exact GELU, direct to d_out (fp32): M=512, N=256, K=512
    gemm_h_nt<3, 0, 1, 0, 0, 0><<<dim3(2, 4, 32), 128>>>(mo_w, 512, 0, 0, xn, 512, 131072L, 0,
                                                         out, 256, 131072L, 0, 512, 1, mo_b, 0, nullptr);
}